// round 6
// baseline (speedup 1.0000x reference)
#include <cuda_runtime.h>
#include <math.h>

// Dims
#define Bx 16
#define Tx 64
#define Sx 32
#define Fx 128
#define Hx 128
#define NHx 4
#define HS 4096      // H*S
#define ROW 262144   // T*S*F
#define T63OFF 258048 // 63*S*F

// Output layout (flattened tuple concat): x_hat1 | z1 | z2 | KL1 | KL2
#define OFF_Z1 4194304
#define OFF_Z2 4196352
#define OFF_KL1 4198400
#define OFF_KL2 4198401

// ---------------- scratch (device globals; no allocation allowed) ----------------
__device__ float g_hid[Bx * Hx * Sx];
__device__ float g_qkv[Bx * NHx * 3 * Hx * Sx];
__device__ float g_att[Bx * NHx * Hx * Sx];
__device__ float g_a[Bx * HS];
__device__ float g_gpart[24 * Bx * Hx];   // 3 gates x 8 k-slices x [16,128]
__device__ float g_mu[Bx * Hx];
__device__ float g_lv[Bx * Hx];
__device__ float g_h2[Bx * Hx];

// ---------------- JAX threefry2x32 (PARTITIONABLE path) -> normal ----------------
// Element i uses 64-bit counter (hi,lo) = (0,i); output word = x0_out ^ x1_out.
__device__ __forceinline__ float tf_normal(unsigned int key1, unsigned int i) {
    unsigned int x0 = 0u, x1 = i;
    unsigned int ks0 = 0u, ks1 = key1, ks2 = key1 ^ 0x1BD11BDAu;
    x0 += ks0; x1 += ks1;
#define TFR(r) { x0 += x1; x1 = (x1 << (r)) | (x1 >> (32 - (r))); x1 ^= x0; }
    TFR(13) TFR(15) TFR(26) TFR(6)
    x0 += ks1; x1 += ks2 + 1u;
    TFR(17) TFR(29) TFR(16) TFR(24)
    x0 += ks2; x1 += ks0 + 2u;
    TFR(13) TFR(15) TFR(26) TFR(6)
    x0 += ks0; x1 += ks1 + 3u;
    TFR(17) TFR(29) TFR(16) TFR(24)
    x0 += ks1; x1 += ks2 + 4u;
    TFR(13) TFR(15) TFR(26) TFR(6)
    x0 += ks2; x1 += ks0 + 5u;
#undef TFR
    unsigned int bits = x0 ^ x1;                     // partitionable: xor of the pair
    float f = __uint_as_float((bits >> 9) | 0x3F800000u) - 1.0f;
    const float lo = -0.99999994f;                   // nextafter(-1, 0)
    float u = f * 2.0f + lo;                         // (1 - lo) rounds to 2.0f in fp32
    u = fmaxf(u, lo);
    return 1.4142135623730951f * erfinvf(u);         // sqrt(2) * erfinv
}

// ---------------- encode: hid^T at t=63 ----------------
// hidT[b][h][s] = sum_f x[b,63,s,f] * w_enc[f,h] + b_enc[h]
__global__ void k_hid(const float* __restrict__ src,   // points at x + 63*S*F (stride ROW per b)
                      const float* __restrict__ w_enc,
                      const float* __restrict__ b_enc) {
    int b = blockIdx.x;
    int h = threadIdx.x & 127;
    int sq = threadIdx.x >> 7;   // 0..3, 8 s each
    const float* xb = src + (size_t)b * ROW;
    for (int s = sq * 8; s < sq * 8 + 8; ++s) {
        float acc = b_enc[h];
        #pragma unroll 16
        for (int f = 0; f < Fx; ++f)
            acc = fmaf(xb[s * Fx + f], w_enc[f * Hx + h], acc);
        g_hid[b * HS + h * Sx + s] = acc;
    }
}

// ---------------- q/k/v per (b, head) ----------------
__global__ void k_qkv(const float* __restrict__ wq, const float* __restrict__ bq,
                      const float* __restrict__ wk, const float* __restrict__ bk,
                      const float* __restrict__ wv, const float* __restrict__ bv) {
    int x = blockIdx.x;          // b*4 + n
    int b = x >> 2, n = x & 3;
    int m = threadIdx.x >> 7;    // 0=q 1=k 2=v  (384 threads)
    int h = threadIdx.x & 127;
    __shared__ float hs[Hx * 33];
    for (int idx = threadIdx.x; idx < HS; idx += 384) {
        int hh = idx >> 5, ss = idx & 31;
        hs[hh * 33 + ss] = g_hid[b * HS + idx];
    }
    __syncthreads();
    const float* W    = (m == 0) ? wq : (m == 1) ? wk : wv;
    const float* bias = (m == 0) ? bq : (m == 1) ? bk : bv;
    const float scale = (m == 0) ? 0.08838834764831845f : 1.0f; // 1/sqrt(128) on q only
    float* out = &g_qkv[(size_t)(x * 3 + m) * HS + h * Sx];
    for (int s = 0; s < Sx; ++s) {
        float acc = bias[n * Sx + s];
        #pragma unroll
        for (int sp = 0; sp < Sx; ++sp)
            acc = fmaf(hs[h * 33 + sp], W[sp * 128 + n * Sx + s], acc);
        out[s] = acc * scale;
    }
}

// ---------------- attention per (b, head) ----------------
__global__ void k_attn() {
    int x = blockIdx.x;            // b*4 + n
    int h = threadIdx.x >> 1;
    int half = threadIdx.x & 1;
    __shared__ float ks[Hx * 33], vs[Hx * 33];
    const float* gq = &g_qkv[(size_t)(x * 3 + 0) * HS];
    const float* gk = &g_qkv[(size_t)(x * 3 + 1) * HS];
    const float* gv = &g_qkv[(size_t)(x * 3 + 2) * HS];
    for (int idx = threadIdx.x; idx < HS; idx += 256) {
        int hh = idx >> 5, ss = idx & 31;
        ks[hh * 33 + ss] = gk[idx];
        vs[hh * 33 + ss] = gv[idx];
    }
    __syncthreads();
    float qreg[16];
    #pragma unroll
    for (int s = 0; s < 16; ++s) qreg[s] = gq[h * Sx + half * 16 + s];

    float m = -1e30f;
    for (int g = 0; g < Hx; ++g) {
        float sc = 0.f;
        #pragma unroll
        for (int s = 0; s < 16; ++s) sc = fmaf(qreg[s], ks[g * 33 + half * 16 + s], sc);
        sc += __shfl_xor_sync(0xffffffffu, sc, 1);
        m = fmaxf(m, sc);
    }
    float l = 0.f;
    float hacc[16];
    #pragma unroll
    for (int s = 0; s < 16; ++s) hacc[s] = 0.f;
    for (int g = 0; g < Hx; ++g) {
        float sc = 0.f;
        #pragma unroll
        for (int s = 0; s < 16; ++s) sc = fmaf(qreg[s], ks[g * 33 + half * 16 + s], sc);
        sc += __shfl_xor_sync(0xffffffffu, sc, 1);
        float p = expf(sc - m);
        l += p;
        #pragma unroll
        for (int s = 0; s < 16; ++s) hacc[s] = fmaf(p, vs[g * 33 + half * 16 + s], hacc[s]);
    }
    float inv = 1.0f / l;
    #pragma unroll
    for (int s = 0; s < 16; ++s)
        g_att[(size_t)x * HS + h * Sx + half * 16 + s] = hacc[s] * inv;
}

// ---------------- head mean + relu -> a ----------------
__global__ void k_amean() {
    int b = blockIdx.x;
    for (int i = threadIdx.x; i < HS; i += 512) {
        float v = g_att[(b * 4 + 0) * HS + i] + g_att[(b * 4 + 1) * HS + i]
                + g_att[(b * 4 + 2) * HS + i] + g_att[(b * 4 + 3) * HS + i];
        g_a[b * HS + i] = fmaxf(0.25f * v, 0.f);
    }
}

// ---------------- LSTM gate partial GEMMs: [16,4096]@[4096,128] x3 ----------------
__global__ void k_gates(const float* __restrict__ Wi, const float* __restrict__ Wg,
                        const float* __restrict__ Wo) {
    int gate = blockIdx.x >> 3;
    int ksl = blockIdx.x & 7;
    int k0 = ksl * 512;
    int j = threadIdx.x;
    __shared__ float a_sm[Bx * 512];
    for (int idx = threadIdx.x; idx < Bx * 512; idx += 128) {
        int b = idx >> 9, rr = idx & 511;
        a_sm[idx] = g_a[b * HS + k0 + rr];
    }
    __syncthreads();
    const float* W = (gate == 0) ? Wi : (gate == 1) ? Wg : Wo;
    float acc[16];
    #pragma unroll
    for (int b = 0; b < 16; ++b) acc[b] = 0.f;
    #pragma unroll 4
    for (int rr = 0; rr < 512; ++rr) {
        float w = W[(size_t)(k0 + rr) * 128 + j];
        #pragma unroll
        for (int b = 0; b < 16; ++b)
            acc[b] = fmaf(a_sm[b * 512 + rr], w, acc[b]);
    }
    #pragma unroll
    for (int b = 0; b < 16; ++b)
        g_gpart[(size_t)blockIdx.x * (Bx * Hx) + b * 128 + j] = acc[b];
}

// ---------------- gate nonlins + h + fc + reparam z ----------------
__global__ void k_finz(const float* __restrict__ w_fc, const float* __restrict__ b_fc,
                       float* __restrict__ z_out, unsigned int key1) {
    int b = blockIdx.x;
    int j = threadIdx.x;
    __shared__ float hv[128];
    float si = 0.f, sg = 0.f, so = 0.f;
    #pragma unroll
    for (int p = 0; p < 8; ++p) {
        si += g_gpart[(0 * 8 + p) * 2048 + b * 128 + j];
        sg += g_gpart[(1 * 8 + p) * 2048 + b * 128 + j];
        so += g_gpart[(2 * 8 + p) * 2048 + b * 128 + j];
    }
    float iv = 1.f / (1.f + expf(-si));
    float gv = tanhf(sg);
    float ov = 1.f / (1.f + expf(-so));
    hv[j] = ov * tanhf(iv * gv);   // c = i*g since c0 = 0
    __syncthreads();
    float mu = b_fc[j], lv = b_fc[128 + j];
    #pragma unroll 8
    for (int k = 0; k < 128; ++k) {
        float hh = hv[k];
        mu = fmaf(hh, w_fc[k * 256 + j], mu);
        lv = fmaf(hh, w_fc[k * 256 + 128 + j], lv);
    }
    g_mu[b * 128 + j] = mu;
    g_lv[b * 128 + j] = lv;
    float eps = tf_normal(key1, (unsigned)(b * 128 + j));
    z_out[b * 128 + j] = mu + eps * expf(0.5f * lv);
}

// ---------------- KL scalar (cancellation-free, double precision) ----------------
// 1 + l - m^2 - e^l == -(m^2 + (expm1(l) - l));  KL = 0.5 * mean(m^2 + expm1(l) - l)
__global__ void k_kl(float* __restrict__ out) {
    __shared__ double red[256];
    double s = 0.0;
    for (int i = threadIdx.x; i < 2048; i += 256) {
        double m = (double)g_mu[i], l = (double)g_lv[i];
        s += m * m + (expm1(l) - l);
    }
    red[threadIdx.x] = s;
    __syncthreads();
    for (int k = 128; k > 0; k >>= 1) {
        if (threadIdx.x < k) red[threadIdx.x] += red[threadIdx.x + k];
        __syncthreads();
    }
    if (threadIdx.x == 0) out[0] = (float)(0.5 * red[0] / 2048.0);
}

// ---------------- decoder small layers ----------------
__global__ void k_dec12(const float* __restrict__ z,
                        const float* __restrict__ w1, const float* __restrict__ b1,
                        const float* __restrict__ w2, const float* __restrict__ b2) {
    __shared__ float zs[2048], h1[2048];
    int j = threadIdx.x;
    for (int i = j; i < 2048; i += 128) zs[i] = z[i];
    __syncthreads();
    for (int b = 0; b < 16; ++b) {
        float acc = b1[j];
        #pragma unroll 8
        for (int k = 0; k < 128; ++k) acc = fmaf(zs[b * 128 + k], w1[k * 128 + j], acc);
        h1[b * 128 + j] = fmaxf(acc, 0.f);
    }
    __syncthreads();
    for (int b = 0; b < 16; ++b) {
        float acc = b2[j];
        #pragma unroll 8
        for (int k = 0; k < 128; ++k) acc = fmaf(h1[b * 128 + k], w2[k * 128 + j], acc);
        g_h2[b * 128 + j] = fmaxf(acc, 0.f);
    }
}

// ---------------- decoder big GEMM: [16,128]@[128,262144] (streams 134MB of w_d3) ----------------
__global__ void k_dec3(const float* __restrict__ w3, const float* __restrict__ b3,
                       float* __restrict__ xhat) {
    __shared__ float hsm[2048];
    for (int i = threadIdx.x; i < 2048; i += 256) hsm[i] = g_h2[i];
    __syncthreads();
    int j4 = blockIdx.x * 256 + threadIdx.x;   // float4 column index (65536 total)
    const float4* w4 = (const float4*)w3;
    float4 bias = ((const float4*)b3)[j4];
    float4 acc[16];
    #pragma unroll
    for (int b = 0; b < 16; ++b) acc[b] = bias;
    #pragma unroll 4
    for (int k = 0; k < 128; ++k) {
        float4 w = w4[(size_t)k * 65536 + j4];
        #pragma unroll
        for (int b = 0; b < 16; ++b) {
            float hb = hsm[b * 128 + k];
            acc[b].x = fmaf(hb, w.x, acc[b].x);
            acc[b].y = fmaf(hb, w.y, acc[b].y);
            acc[b].z = fmaf(hb, w.z, acc[b].z);
            acc[b].w = fmaf(hb, w.w, acc[b].w);
        }
    }
    float4* out4 = (float4*)xhat;
    #pragma unroll
    for (int b = 0; b < 16; ++b) out4[(size_t)b * 65536 + j4] = acc[b];
}

// ---------------- launch ----------------
extern "C" void kernel_launch(void* const* d_in, const int* in_sizes, int n_in,
                              void* d_out, int out_size) {
    const float* x     = (const float*)d_in[0];
    const float* w_enc = (const float*)d_in[1];
    const float* b_enc = (const float*)d_in[2];
    const float* wq = (const float*)d_in[3];
    const float* bq = (const float*)d_in[4];
    const float* wk = (const float*)d_in[5];
    const float* bk = (const float*)d_in[6];
    const float* wv = (const float*)d_in[7];
    const float* bv = (const float*)d_in[8];
    const float* W_ii = (const float*)d_in[9];
    // d_in[10..12]: W_hi, W_if, W_hf  — unused (c0 = 0 kills f gate and all W_h*)
    const float* W_ig = (const float*)d_in[13];
    // d_in[14]: W_hg unused
    const float* W_io = (const float*)d_in[15];
    // d_in[16]: W_ho unused
    const float* w_fc = (const float*)d_in[17];
    const float* b_fc = (const float*)d_in[18];
    const float* w_d1 = (const float*)d_in[19];
    const float* b_d1 = (const float*)d_in[20];
    const float* w_d2 = (const float*)d_in[21];
    const float* b_d2 = (const float*)d_in[22];
    const float* w_d3 = (const float*)d_in[23];
    const float* b_d3 = (const float*)d_in[24];

    float* out  = (float*)d_out;
    float* xhat = out;
    float* z1   = out + OFF_Z1;
    float* z2   = out + OFF_Z2;
    float* kl1  = out + OFF_KL1;
    float* kl2  = out + OFF_KL2;

    // ---- encode 1 (only t = T-1 matters) ----
    k_hid<<<16, 512>>>(x + T63OFF, w_enc, b_enc);
    k_qkv<<<64, 384>>>(wq, bq, wk, bk, wv, bv);
    k_attn<<<64, 256>>>();
    k_amean<<<16, 512>>>();
    k_gates<<<24, 128>>>(W_ii, W_ig, W_io);
    k_finz<<<16, 128>>>(w_fc, b_fc, z1, 1u);
    k_kl<<<1, 256>>>(kl1);

    // ---- decode ----
    k_dec12<<<1, 128>>>(z1, w_d1, b_d1, w_d2, b_d2);
    k_dec3<<<256, 256>>>(w_d3, b_d3, xhat);

    // ---- encode 2 on x_hat (same layout: row stride ROW, t=63 offset) ----
    k_hid<<<16, 512>>>(xhat + T63OFF, w_enc, b_enc);
    k_qkv<<<64, 384>>>(wq, bq, wk, bk, wv, bv);
    k_attn<<<64, 256>>>();
    k_amean<<<16, 512>>>();
    k_gates<<<24, 128>>>(W_ii, W_ig, W_io);
    k_finz<<<16, 128>>>(w_fc, b_fc, z2, 2u);
    k_kl<<<1, 256>>>(kl2);
}

// round 7
// speedup vs baseline: 1.1028x; 1.1028x over previous
#include <cuda_runtime.h>
#include <math.h>

// Dims
#define Bx 16
#define Tx 64
#define Sx 32
#define Fx 128
#define Hx 128
#define NHx 4
#define HS 4096      // H*S
#define ROW 262144   // T*S*F
#define T63OFF 258048 // 63*S*F

// Output layout (flattened tuple concat): x_hat1 | z1 | z2 | KL1 | KL2
#define OFF_Z1 4194304
#define OFF_Z2 4196352
#define OFF_KL1 4198400
#define OFF_KL2 4198401

#define GSLICES 32                    // k-slices per gate in k_gates2
#define ENC_SMEM (4 * 128 * 33 * 4)   // hid,q,k,v each [128][33] floats

// ---------------- scratch (device globals; no allocation allowed) ----------------
__device__ float g_att[Bx * NHx * Hx * Sx];
__device__ float g_gpart[3 * GSLICES * Bx * Hx];  // 3 gates x 32 slices x [16,128]
__device__ float g_mu[Bx * Hx];
__device__ float g_lv[Bx * Hx];
__device__ float g_h2[Bx * Hx];

// ---------------- JAX threefry2x32 (partitionable) -> normal ----------------
__device__ __forceinline__ float tf_normal(unsigned int key1, unsigned int i) {
    unsigned int x0 = 0u, x1 = i;
    unsigned int ks0 = 0u, ks1 = key1, ks2 = key1 ^ 0x1BD11BDAu;
    x0 += ks0; x1 += ks1;
#define TFR(r) { x0 += x1; x1 = (x1 << (r)) | (x1 >> (32 - (r))); x1 ^= x0; }
    TFR(13) TFR(15) TFR(26) TFR(6)
    x0 += ks1; x1 += ks2 + 1u;
    TFR(17) TFR(29) TFR(16) TFR(24)
    x0 += ks2; x1 += ks0 + 2u;
    TFR(13) TFR(15) TFR(26) TFR(6)
    x0 += ks0; x1 += ks1 + 3u;
    TFR(17) TFR(29) TFR(16) TFR(24)
    x0 += ks1; x1 += ks2 + 4u;
    TFR(13) TFR(15) TFR(26) TFR(6)
    x0 += ks2; x1 += ks0 + 5u;
#undef TFR
    unsigned int bits = x0 ^ x1;
    float f = __uint_as_float((bits >> 9) | 0x3F800000u) - 1.0f;
    const float lo = -0.99999994f;
    float u = f * 2.0f + lo;
    u = fmaxf(u, lo);
    return 1.4142135623730951f * erfinvf(u);
}

// ---------------- fused encode: hid + qkv + attention per (b, head) ----------------
// grid 64 = b*4+n, 384 threads, 68KB dynamic smem.
__global__ void k_enc(const float* __restrict__ src,   // x (or xhat) + 63*S*F; stride ROW per b
                      const float* __restrict__ w_enc, const float* __restrict__ b_enc,
                      const float* __restrict__ wq, const float* __restrict__ bq,
                      const float* __restrict__ wk, const float* __restrict__ bk,
                      const float* __restrict__ wv, const float* __restrict__ bv) {
    extern __shared__ float sm[];
    float* hid = sm;                 // [128][33]
    float* qs  = sm + 128 * 33;      // [128][33]
    float* ks  = sm + 2 * 128 * 33;
    float* vs  = sm + 3 * 128 * 33;
    int xid = blockIdx.x;            // b*4 + n
    int b = xid >> 2, n = xid & 3;
    int tid = threadIdx.x;
    const float* xb = src + (size_t)b * ROW;

    // Phase 1: hid[h][s] = b_enc[h] + sum_f x[s,f] * w_enc[f,h]
    for (int idx = tid; idx < HS; idx += 384) {
        int h = idx >> 5, s = idx & 31;
        float acc = b_enc[h];
        #pragma unroll 16
        for (int f = 0; f < Fx; ++f)
            acc = fmaf(xb[s * Fx + f], w_enc[f * Hx + h], acc);
        hid[h * 33 + s] = acc;
    }
    __syncthreads();

    // Phase 2: q/k/v[h][s] = bias[n*32+s] + sum_sp hid[h][sp] * W[sp*128 + n*32+s]
    {
        int m = tid >> 7;            // 0=q 1=k 2=v
        int h = tid & 127;
        const float* W    = (m == 0) ? wq : (m == 1) ? wk : wv;
        const float* bias = (m == 0) ? bq : (m == 1) ? bk : bv;
        float* dst        = (m == 0) ? qs : (m == 1) ? ks : vs;
        const float scale = (m == 0) ? 0.08838834764831845f : 1.0f;
        for (int s = 0; s < Sx; ++s) {
            float acc = bias[n * Sx + s];
            #pragma unroll
            for (int sp = 0; sp < Sx; ++sp)
                acc = fmaf(hid[h * 33 + sp], W[sp * 128 + n * Sx + s], acc);
            dst[h * 33 + s] = acc * scale;
        }
    }
    __syncthreads();

    // Phase 3: attention (first 256 threads: thread = h*2 + half)
    if (tid < 256) {
        int h = tid >> 1;
        int half = tid & 1;
        float qreg[16];
        #pragma unroll
        for (int s = 0; s < 16; ++s) qreg[s] = qs[h * 33 + half * 16 + s];

        float m = -1e30f;
        for (int g = 0; g < Hx; ++g) {
            float sc = 0.f;
            #pragma unroll
            for (int s = 0; s < 16; ++s) sc = fmaf(qreg[s], ks[g * 33 + half * 16 + s], sc);
            sc += __shfl_xor_sync(0xffffffffu, sc, 1);
            m = fmaxf(m, sc);
        }
        float l = 0.f;
        float hacc[16];
        #pragma unroll
        for (int s = 0; s < 16; ++s) hacc[s] = 0.f;
        for (int g = 0; g < Hx; ++g) {
            float sc = 0.f;
            #pragma unroll
            for (int s = 0; s < 16; ++s) sc = fmaf(qreg[s], ks[g * 33 + half * 16 + s], sc);
            sc += __shfl_xor_sync(0xffffffffu, sc, 1);
            float p = expf(sc - m);
            l += p;
            #pragma unroll
            for (int s = 0; s < 16; ++s) hacc[s] = fmaf(p, vs[g * 33 + half * 16 + s], hacc[s]);
        }
        float inv = 1.0f / l;
        #pragma unroll
        for (int s = 0; s < 16; ++s)
            g_att[(size_t)xid * HS + h * Sx + half * 16 + s] = hacc[s] * inv;
    }
}

// ---------------- fused head-mean+relu + gate partial GEMMs ----------------
// grid 96 = gate*32 + slice; 128 threads. Each slice covers 128 k-rows.
__global__ void k_gates2(const float* __restrict__ Wi, const float* __restrict__ Wg,
                         const float* __restrict__ Wo) {
    int gate = blockIdx.x >> 5;      // 0..2
    int ksl  = blockIdx.x & 31;      // 0..31
    int k0 = ksl * 128;
    int j = threadIdx.x;
    __shared__ float a_sm[Bx * 128];
    for (int idx = threadIdx.x; idx < Bx * 128; idx += 128) {
        int b = idx >> 7, rr = idx & 127;
        float v = g_att[(size_t)(b * 4 + 0) * HS + k0 + rr]
                + g_att[(size_t)(b * 4 + 1) * HS + k0 + rr]
                + g_att[(size_t)(b * 4 + 2) * HS + k0 + rr]
                + g_att[(size_t)(b * 4 + 3) * HS + k0 + rr];
        a_sm[idx] = fmaxf(0.25f * v, 0.f);
    }
    __syncthreads();
    const float* W = (gate == 0) ? Wi : (gate == 1) ? Wg : Wo;
    float acc[16];
    #pragma unroll
    for (int b = 0; b < 16; ++b) acc[b] = 0.f;
    #pragma unroll 8
    for (int rr = 0; rr < 128; ++rr) {
        float w = W[(size_t)(k0 + rr) * 128 + j];
        #pragma unroll
        for (int b = 0; b < 16; ++b)
            acc[b] = fmaf(a_sm[b * 128 + rr], w, acc[b]);
    }
    #pragma unroll
    for (int b = 0; b < 16; ++b)
        g_gpart[(size_t)blockIdx.x * (Bx * Hx) + b * 128 + j] = acc[b];
}

// ---------------- gate nonlins + h + fc + reparam z ----------------
__global__ void k_finz(const float* __restrict__ w_fc, const float* __restrict__ b_fc,
                       float* __restrict__ z_out, unsigned int key1) {
    int b = blockIdx.x;
    int j = threadIdx.x;
    __shared__ float hv[128];
    float si = 0.f, sg = 0.f, so = 0.f;
    #pragma unroll 8
    for (int p = 0; p < GSLICES; ++p) {
        si += g_gpart[(size_t)(0 * GSLICES + p) * 2048 + b * 128 + j];
        sg += g_gpart[(size_t)(1 * GSLICES + p) * 2048 + b * 128 + j];
        so += g_gpart[(size_t)(2 * GSLICES + p) * 2048 + b * 128 + j];
    }
    float iv = 1.f / (1.f + expf(-si));
    float gv = tanhf(sg);
    float ov = 1.f / (1.f + expf(-so));
    hv[j] = ov * tanhf(iv * gv);     // c = i*g since c0 = 0
    __syncthreads();
    float mu = b_fc[j], lv = b_fc[128 + j];
    #pragma unroll 8
    for (int k = 0; k < 128; ++k) {
        float hh = hv[k];
        mu = fmaf(hh, w_fc[k * 256 + j], mu);
        lv = fmaf(hh, w_fc[k * 256 + 128 + j], lv);
    }
    g_mu[b * 128 + j] = mu;
    g_lv[b * 128 + j] = lv;
    float eps = tf_normal(key1, (unsigned)(b * 128 + j));
    z_out[b * 128 + j] = mu + eps * expf(0.5f * lv);
}

// ---------------- KL scalar (cancellation-free, double precision) ----------------
__global__ void k_kl(float* __restrict__ out) {
    __shared__ double red[256];
    double s = 0.0;
    for (int i = threadIdx.x; i < 2048; i += 256) {
        double m = (double)g_mu[i], l = (double)g_lv[i];
        s += m * m + (expm1(l) - l);
    }
    red[threadIdx.x] = s;
    __syncthreads();
    for (int k = 128; k > 0; k >>= 1) {
        if (threadIdx.x < k) red[threadIdx.x] += red[threadIdx.x + k];
        __syncthreads();
    }
    if (threadIdx.x == 0) out[0] = (float)(0.5 * red[0] / 2048.0);
}

// ---------------- decoder small layers (per-b blocks) ----------------
__global__ void k_dec12(const float* __restrict__ z,
                        const float* __restrict__ w1, const float* __restrict__ b1,
                        const float* __restrict__ w2, const float* __restrict__ b2) {
    int b = blockIdx.x;
    int j = threadIdx.x;
    __shared__ float zs[128], h1[128];
    zs[j] = z[b * 128 + j];
    __syncthreads();
    float acc = b1[j];
    #pragma unroll 8
    for (int k = 0; k < 128; ++k) acc = fmaf(zs[k], w1[k * 128 + j], acc);
    h1[j] = fmaxf(acc, 0.f);
    __syncthreads();
    acc = b2[j];
    #pragma unroll 8
    for (int k = 0; k < 128; ++k) acc = fmaf(h1[k], w2[k * 128 + j], acc);
    g_h2[b * 128 + j] = fmaxf(acc, 0.f);
}

// ---------------- decoder big GEMM: [16,128]@[128,262144] (streams 134MB) ----------------
// grid 512 x 128 threads; each thread owns one float4 column, k-unroll 8 for MLP.
__global__ void k_dec3(const float* __restrict__ w3, const float* __restrict__ b3,
                       float* __restrict__ xhat) {
    __shared__ float hsm[2048];
    for (int i = threadIdx.x; i < 2048; i += 128) hsm[i] = g_h2[i];
    __syncthreads();
    int j4 = blockIdx.x * 128 + threadIdx.x;   // float4 column index (65536 total)
    const float4* w4 = (const float4*)w3;
    float4 bias = ((const float4*)b3)[j4];
    float4 acc[16];
    #pragma unroll
    for (int b = 0; b < 16; ++b) acc[b] = bias;
    #pragma unroll 8
    for (int k = 0; k < 128; ++k) {
        float4 w = w4[(size_t)k * 65536 + j4];
        #pragma unroll
        for (int b = 0; b < 16; ++b) {
            float hb = hsm[b * 128 + k];
            acc[b].x = fmaf(hb, w.x, acc[b].x);
            acc[b].y = fmaf(hb, w.y, acc[b].y);
            acc[b].z = fmaf(hb, w.z, acc[b].z);
            acc[b].w = fmaf(hb, w.w, acc[b].w);
        }
    }
    float4* out4 = (float4*)xhat;
    #pragma unroll
    for (int b = 0; b < 16; ++b) out4[(size_t)b * 65536 + j4] = acc[b];
}

// ---------------- launch ----------------
extern "C" void kernel_launch(void* const* d_in, const int* in_sizes, int n_in,
                              void* d_out, int out_size) {
    const float* x     = (const float*)d_in[0];
    const float* w_enc = (const float*)d_in[1];
    const float* b_enc = (const float*)d_in[2];
    const float* wq = (const float*)d_in[3];
    const float* bq = (const float*)d_in[4];
    const float* wk = (const float*)d_in[5];
    const float* bk = (const float*)d_in[6];
    const float* wv = (const float*)d_in[7];
    const float* bv = (const float*)d_in[8];
    const float* W_ii = (const float*)d_in[9];
    // d_in[10..12]: W_hi, W_if, W_hf unused (c0 = 0 kills f gate and all W_h*)
    const float* W_ig = (const float*)d_in[13];
    const float* W_io = (const float*)d_in[15];
    const float* w_fc = (const float*)d_in[17];
    const float* b_fc = (const float*)d_in[18];
    const float* w_d1 = (const float*)d_in[19];
    const float* b_d1 = (const float*)d_in[20];
    const float* w_d2 = (const float*)d_in[21];
    const float* b_d2 = (const float*)d_in[22];
    const float* w_d3 = (const float*)d_in[23];
    const float* b_d3 = (const float*)d_in[24];

    float* out  = (float*)d_out;
    float* xhat = out;
    float* z1   = out + OFF_Z1;
    float* z2   = out + OFF_Z2;
    float* kl1  = out + OFF_KL1;
    float* kl2  = out + OFF_KL2;

    cudaFuncSetAttribute(k_enc, cudaFuncAttributeMaxDynamicSharedMemorySize, ENC_SMEM);

    // ---- encode 1 (only t = T-1 matters) ----
    k_enc<<<64, 384, ENC_SMEM>>>(x + T63OFF, w_enc, b_enc, wq, bq, wk, bk, wv, bv);
    k_gates2<<<96, 128>>>(W_ii, W_ig, W_io);
    k_finz<<<16, 128>>>(w_fc, b_fc, z1, 1u);
    k_kl<<<1, 256>>>(kl1);

    // ---- decode ----
    k_dec12<<<16, 128>>>(z1, w_d1, b_d1, w_d2, b_d2);
    k_dec3<<<512, 128>>>(w_d3, b_d3, xhat);

    // ---- encode 2 on x_hat ----
    k_enc<<<64, 384, ENC_SMEM>>>(xhat + T63OFF, w_enc, b_enc, wq, bq, wk, bk, wv, bv);
    k_gates2<<<96, 128>>>(W_ii, W_ig, W_io);
    k_finz<<<16, 128>>>(w_fc, b_fc, z2, 2u);
    k_kl<<<1, 256>>>(kl2);
}

// round 9
// speedup vs baseline: 2.5686x; 2.3291x over previous
#include <cuda_runtime.h>
#include <math.h>

// Dims
#define Bx 16
#define Tx 64
#define Sx 32
#define Fx 128
#define Hx 128
#define NHx 4
#define HS 4096      // H*S
#define ROW 262144   // T*S*F
#define T63OFF 258048 // 63*S*F

// Output layout (flattened tuple concat): x_hat1 | z1 | z2 | KL1 | KL2
#define OFF_Z1 4194304
#define OFF_Z2 4196352
#define OFF_KL1 4198400
#define OFF_KL2 4198401

#define GSLICES 64                          // k-slices per gate in k_gates2 (64 rows each)
// smem: hid[128*33] + q/k/v[128*33]*3 + scores[128*130]
#define ENC_SMEM ((4 * 128 * 33 + 128 * 130) * 4)

// ---------------- scratch (device globals; no allocation allowed) ----------------
__device__ float g_att[Bx * NHx * Hx * Sx];
__device__ float g_gpart[3 * GSLICES * Bx * Hx];
__device__ float g_h2[Bx * Hx];
__device__ double g_klpart[Bx];

// ---------------- JAX threefry2x32 (partitionable) -> normal ----------------
__device__ __forceinline__ float tf_normal(unsigned int key1, unsigned int i) {
    unsigned int x0 = 0u, x1 = i;
    unsigned int ks0 = 0u, ks1 = key1, ks2 = key1 ^ 0x1BD11BDAu;
    x0 += ks0; x1 += ks1;
#define TFR(r) { x0 += x1; x1 = (x1 << (r)) | (x1 >> (32 - (r))); x1 ^= x0; }
    TFR(13) TFR(15) TFR(26) TFR(6)
    x0 += ks1; x1 += ks2 + 1u;
    TFR(17) TFR(29) TFR(16) TFR(24)
    x0 += ks2; x1 += ks0 + 2u;
    TFR(13) TFR(15) TFR(26) TFR(6)
    x0 += ks0; x1 += ks1 + 3u;
    TFR(17) TFR(29) TFR(16) TFR(24)
    x0 += ks1; x1 += ks2 + 4u;
    TFR(13) TFR(15) TFR(26) TFR(6)
    x0 += ks2; x1 += ks0 + 5u;
#undef TFR
    unsigned int bits = x0 ^ x1;
    float f = __uint_as_float((bits >> 9) | 0x3F800000u) - 1.0f;
    const float lo = -0.99999994f;
    float u = f * 2.0f + lo;
    u = fmaxf(u, lo);
    return 1.4142135623730951f * erfinvf(u);
}

// ---------------- fused encode: hid + qkv + attention per (b, head) ----------------
// grid 64 = b*4+n, 384 threads, ~132KB dynamic smem (1 block/SM; grid < #SMs).
__global__ void __launch_bounds__(384)
k_enc(const float* __restrict__ src,   // x (or xhat) + 63*S*F; stride ROW per b
      const float* __restrict__ w_enc, const float* __restrict__ b_enc,
      const float* __restrict__ wq, const float* __restrict__ bq,
      const float* __restrict__ wk, const float* __restrict__ bk,
      const float* __restrict__ wv, const float* __restrict__ bv) {
    extern __shared__ float sm[];
    float* hid = sm;                     // [128][33]
    float* qs  = sm + 128 * 33;
    float* ks  = sm + 2 * 128 * 33;
    float* vs  = sm + 3 * 128 * 33;
    float* scr = sm + 4 * 128 * 33;      // [128][130] score cache
    int xid = blockIdx.x;                // b*4 + n
    int b = xid >> 2, n = xid & 3;
    int tid = threadIdx.x;
    const float* xb = src + (size_t)b * ROW;

    // Phase 1: hid[h][s] = b_enc[h] + sum_f x[s,f] * w_enc[f,h]  (2-way s ILP per thread)
    {
        int h = tid & 127;
        int grp = tid >> 7;              // 0..2
        int s0 = (grp == 0) ? 0 : (grp == 1 ? 11 : 22);
        int s1 = (grp == 0) ? 11 : (grp == 1 ? 22 : 32);
        float be = b_enc[h];
        int s = s0;
        for (; s + 2 <= s1; s += 2) {
            float a0 = be, a1 = be;
            const float* x0 = xb + s * Fx;
            const float* x1 = xb + (s + 1) * Fx;
            #pragma unroll 8
            for (int f = 0; f < Fx; ++f) {
                float w = w_enc[f * Hx + h];
                a0 = fmaf(x0[f], w, a0);
                a1 = fmaf(x1[f], w, a1);
            }
            hid[h * 33 + s] = a0;
            hid[h * 33 + s + 1] = a1;
        }
        if (s < s1) {
            float a0 = be;
            const float* x0 = xb + s * Fx;
            #pragma unroll 8
            for (int f = 0; f < Fx; ++f)
                a0 = fmaf(x0[f], w_enc[f * Hx + h], a0);
            hid[h * 33 + s] = a0;
        }
    }
    __syncthreads();

    // Phase 2: q/k/v[h][s] = bias + sum_sp hid[h][sp]*W[sp*128 + n*32+s]  (2-way s ILP)
    {
        int m = tid >> 7;                // 0=q 1=k 2=v
        int h = tid & 127;
        const float* W    = (m == 0) ? wq : (m == 1) ? wk : wv;
        const float* bias = (m == 0) ? bq : (m == 1) ? bk : bv;
        float* dst        = (m == 0) ? qs : (m == 1) ? ks : vs;
        const float scale = (m == 0) ? 0.08838834764831845f : 1.0f;
        for (int s = 0; s < Sx; s += 2) {
            float a0 = bias[n * Sx + s];
            float a1 = bias[n * Sx + s + 1];
            #pragma unroll
            for (int sp = 0; sp < Sx; ++sp) {
                float hval = hid[h * 33 + sp];
                a0 = fmaf(hval, W[sp * 128 + n * Sx + s], a0);
                a1 = fmaf(hval, W[sp * 128 + n * Sx + s + 1], a1);
            }
            dst[h * 33 + s] = a0 * scale;
            dst[h * 33 + s + 1] = a1 * scale;
        }
    }
    __syncthreads();

    // Phase 3: attention. threads 0..255: thread = h*2 + half.
    // Pass 1: score once (paired g, 2 indep chains), cache in smem, track max.
    // Pass 2: exp + v-accumulate from cache (no recompute, no shfl).
    if (tid < 256) {
        int h = tid >> 1;
        int half = tid & 1;
        int off = half * 16;
        float qreg[16];
        #pragma unroll
        for (int s = 0; s < 16; ++s) qreg[s] = qs[h * 33 + off + s];

        float m = -1e30f;
        for (int g = 0; g < Hx; g += 2) {
            float sc0 = 0.f, sc1 = 0.f;
            #pragma unroll
            for (int s = 0; s < 16; ++s) {
                sc0 = fmaf(qreg[s], ks[g * 33 + off + s], sc0);
                sc1 = fmaf(qreg[s], ks[(g + 1) * 33 + off + s], sc1);
            }
            sc0 += __shfl_xor_sync(0xffffffffu, sc0, 1);
            sc1 += __shfl_xor_sync(0xffffffffu, sc1, 1);
            if (half == 0) {
                scr[h * 130 + g] = sc0;
                scr[h * 130 + g + 1] = sc1;
            }
            m = fmaxf(m, fmaxf(sc0, sc1));
        }
        __syncwarp();

        float l = 0.f;
        float hacc[16];
        #pragma unroll
        for (int s = 0; s < 16; ++s) hacc[s] = 0.f;
        for (int g = 0; g < Hx; ++g) {
            float p = __expf(scr[h * 130 + g] - m);
            l += p;
            #pragma unroll
            for (int s = 0; s < 16; ++s)
                hacc[s] = fmaf(p, vs[g * 33 + off + s], hacc[s]);
        }
        float inv = 1.0f / l;
        #pragma unroll
        for (int s = 0; s < 16; ++s)
            g_att[(size_t)xid * HS + h * Sx + off + s] = hacc[s] * inv;
    }
}

// ---------------- fused head-mean+relu + gate partial GEMMs ----------------
// grid 192 = gate*64 + slice; 128 threads. Each slice covers 64 k-rows.
__global__ void k_gates2(const float* __restrict__ Wi, const float* __restrict__ Wg,
                         const float* __restrict__ Wo) {
    int gate = blockIdx.x >> 6;          // 0..2
    int ksl  = blockIdx.x & 63;          // 0..63
    int k0 = ksl * 64;
    int j = threadIdx.x;
    __shared__ float a_sm[Bx * 64];
    for (int idx = threadIdx.x; idx < Bx * 64; idx += 128) {
        int b = idx >> 6, rr = idx & 63;
        float v = g_att[(size_t)(b * 4 + 0) * HS + k0 + rr]
                + g_att[(size_t)(b * 4 + 1) * HS + k0 + rr]
                + g_att[(size_t)(b * 4 + 2) * HS + k0 + rr]
                + g_att[(size_t)(b * 4 + 3) * HS + k0 + rr];
        a_sm[idx] = fmaxf(0.25f * v, 0.f);
    }
    __syncthreads();
    const float* W = (gate == 0) ? Wi : (gate == 1) ? Wg : Wo;
    float acc[16];
    #pragma unroll
    for (int b = 0; b < 16; ++b) acc[b] = 0.f;
    #pragma unroll 8
    for (int rr = 0; rr < 64; ++rr) {
        float w = W[(size_t)(k0 + rr) * 128 + j];
        #pragma unroll
        for (int b = 0; b < 16; ++b)
            acc[b] = fmaf(a_sm[b * 64 + rr], w, acc[b]);
    }
    #pragma unroll
    for (int b = 0; b < 16; ++b)
        g_gpart[(size_t)blockIdx.x * (Bx * Hx) + b * 128 + j] = acc[b];
}

// ---------------- gate nonlins + h + fc + reparam z + KL partial (+ optional dec12) ----------------
__global__ void k_finz(const float* __restrict__ w_fc, const float* __restrict__ b_fc,
                       float* __restrict__ z_out, unsigned int key1,
                       const float* __restrict__ w1, const float* __restrict__ b1,
                       const float* __restrict__ w2, const float* __restrict__ b2,
                       int do_decode) {
    int b = blockIdx.x;
    int j = threadIdx.x;
    __shared__ float hv[128];
    __shared__ double dred[128];
    float si = 0.f, sg = 0.f, so = 0.f;
    #pragma unroll 8
    for (int p = 0; p < GSLICES; ++p) {
        si += g_gpart[(size_t)(0 * GSLICES + p) * 2048 + b * 128 + j];
        sg += g_gpart[(size_t)(1 * GSLICES + p) * 2048 + b * 128 + j];
        so += g_gpart[(size_t)(2 * GSLICES + p) * 2048 + b * 128 + j];
    }
    float iv = 1.f / (1.f + expf(-si));
    float gv = tanhf(sg);
    float ov = 1.f / (1.f + expf(-so));
    hv[j] = ov * tanhf(iv * gv);         // c = i*g since c0 = 0
    __syncthreads();
    float mu = b_fc[j], lv = b_fc[128 + j];
    #pragma unroll 8
    for (int k = 0; k < 128; ++k) {
        float hh = hv[k];
        mu = fmaf(hh, w_fc[k * 256 + j], mu);
        lv = fmaf(hh, w_fc[k * 256 + 128 + j], lv);
    }
    // KL partial: m^2 + (expm1(l) - l), cancellation-free, double
    {
        double md = (double)mu, ld = (double)lv;
        dred[j] = md * md + (expm1(ld) - ld);
    }
    float eps = tf_normal(key1, (unsigned)(b * 128 + j));
    float z = mu + eps * expf(0.5f * lv);
    z_out[b * 128 + j] = z;
    __syncthreads();
    for (int k = 64; k > 0; k >>= 1) {
        if (j < k) dred[j] += dred[j + k];
        __syncthreads();
    }
    if (j == 0) g_klpart[b] = dred[0];

    if (do_decode) {
        // dec layer 1+2 fused (reuse hv as z then h1 buffer)
        __shared__ float zsm[128], h1[128];
        zsm[j] = z;
        __syncthreads();
        float acc = b1[j];
        #pragma unroll 8
        for (int k = 0; k < 128; ++k) acc = fmaf(zsm[k], w1[k * 128 + j], acc);
        h1[j] = fmaxf(acc, 0.f);
        __syncthreads();
        acc = b2[j];
        #pragma unroll 8
        for (int k = 0; k < 128; ++k) acc = fmaf(h1[k], w2[k * 128 + j], acc);
        g_h2[b * 128 + j] = fmaxf(acc, 0.f);
    }
}

// ---------------- KL final sum: 16 doubles -> scalar ----------------
__global__ void k_klsum(float* __restrict__ out) {
    if (threadIdx.x == 0) {
        double s = 0.0;
        #pragma unroll
        for (int b = 0; b < Bx; ++b) s += g_klpart[b];
        out[0] = (float)(0.5 * s / 2048.0);
    }
}

// ---------------- decoder big GEMM: [16,128]@[128,262144] (streams 134MB) ----------------
__global__ void __launch_bounds__(128)
k_dec3(const float* __restrict__ w3, const float* __restrict__ b3,
       float* __restrict__ xhat) {
    __shared__ float hsm[2048];
    for (int i = threadIdx.x; i < 2048; i += 128) hsm[i] = g_h2[i];
    __syncthreads();
    int j4 = blockIdx.x * 128 + threadIdx.x;   // float4 column index (65536 total)
    const float4* w4 = (const float4*)w3;
    float4 bias = ((const float4*)b3)[j4];
    float4 acc[16];
    #pragma unroll
    for (int b = 0; b < 16; ++b) acc[b] = bias;
    #pragma unroll 4
    for (int k = 0; k < 128; ++k) {
        float4 w = w4[(size_t)k * 65536 + j4];
        #pragma unroll
        for (int b = 0; b < 16; ++b) {
            float hb = hsm[b * 128 + k];
            acc[b].x = fmaf(hb, w.x, acc[b].x);
            acc[b].y = fmaf(hb, w.y, acc[b].y);
            acc[b].z = fmaf(hb, w.z, acc[b].z);
            acc[b].w = fmaf(hb, w.w, acc[b].w);
        }
    }
    float4* out4 = (float4*)xhat;
    #pragma unroll
    for (int b = 0; b < 16; ++b) out4[(size_t)b * 65536 + j4] = acc[b];
}

// ---------------- launch ----------------
extern "C" void kernel_launch(void* const* d_in, const int* in_sizes, int n_in,
                              void* d_out, int out_size) {
    const float* x     = (const float*)d_in[0];
    const float* w_enc = (const float*)d_in[1];
    const float* b_enc = (const float*)d_in[2];
    const float* wq = (const float*)d_in[3];
    const float* bq = (const float*)d_in[4];
    const float* wk = (const float*)d_in[5];
    const float* bk = (const float*)d_in[6];
    const float* wv = (const float*)d_in[7];
    const float* bv = (const float*)d_in[8];
    const float* W_ii = (const float*)d_in[9];
    // d_in[10..12]: W_hi, W_if, W_hf unused (c0 = 0 kills f gate and all W_h*)
    const float* W_ig = (const float*)d_in[13];
    const float* W_io = (const float*)d_in[15];
    const float* w_fc = (const float*)d_in[17];
    const float* b_fc = (const float*)d_in[18];
    const float* w_d1 = (const float*)d_in[19];
    const float* b_d1 = (const float*)d_in[20];
    const float* w_d2 = (const float*)d_in[21];
    const float* b_d2 = (const float*)d_in[22];
    const float* w_d3 = (const float*)d_in[23];
    const float* b_d3 = (const float*)d_in[24];

    float* out  = (float*)d_out;
    float* xhat = out;
    float* z1   = out + OFF_Z1;
    float* z2   = out + OFF_Z2;
    float* kl1  = out + OFF_KL1;
    float* kl2  = out + OFF_KL2;

    cudaFuncSetAttribute(k_enc, cudaFuncAttributeMaxDynamicSharedMemorySize, ENC_SMEM);

    // ---- encode 1 (only t = T-1 matters) ----
    k_enc<<<64, 384, ENC_SMEM>>>(x + T63OFF, w_enc, b_enc, wq, bq, wk, bk, wv, bv);
    k_gates2<<<192, 128>>>(W_ii, W_ig, W_io);
    k_finz<<<16, 128>>>(w_fc, b_fc, z1, 1u, w_d1, b_d1, w_d2, b_d2, 1);
    k_klsum<<<1, 32>>>(kl1);

    // ---- decode (dec12 fused into finz above) ----
    k_dec3<<<512, 128>>>(w_d3, b_d3, xhat);

    // ---- encode 2 on x_hat ----
    k_enc<<<64, 384, ENC_SMEM>>>(xhat + T63OFF, w_enc, b_enc, wq, bq, wk, bk, wv, bv);
    k_gates2<<<192, 128>>>(W_ii, W_ig, W_io);
    k_finz<<<16, 128>>>(w_fc, b_fc, z2, 2u, w_d1, b_d1, w_d2, b_d2, 0);
    k_klsum<<<1, 32>>>(kl2);
}

// round 10
// speedup vs baseline: 2.5690x; 1.0002x over previous
#include <cuda_runtime.h>
#include <math.h>

// Dims
#define Bx 16
#define Tx 64
#define Sx 32
#define Fx 128
#define Hx 128
#define NHx 4
#define HS 4096      // H*S
#define ROW 262144   // T*S*F
#define T63OFF 258048 // 63*S*F

// Output layout (flattened tuple concat): x_hat1 | z1 | z2 | KL1 | KL2
#define OFF_Z1 4194304
#define OFF_Z2 4196352
#define OFF_KL1 4198400
#define OFF_KL2 4198401

#define GSLICES 64                          // k-slices per gate in k_gates2 (64 rows each)
// smem: hid,q,k,v each [128][33] floats (single-pass attention needs no score cache)
#define ENC_SMEM (4 * 128 * 33 * 4)

// float4 column split for k_dec3: t63 slice = [64512, 65536), rest = [0, 64512)
#define J4_T63 64512
#define J4_ALL 65536

// ---------------- scratch (device globals; no allocation allowed) ----------------
__device__ float g_att[Bx * NHx * Hx * Sx];
__device__ float g_gpart[3 * GSLICES * Bx * Hx];
__device__ float g_h2[Bx * Hx];
__device__ double g_klpart1[Bx];
__device__ double g_klpart2[Bx];

// ---------------- JAX threefry2x32 (partitionable) -> normal ----------------
__device__ __forceinline__ float tf_normal(unsigned int key1, unsigned int i) {
    unsigned int x0 = 0u, x1 = i;
    unsigned int ks0 = 0u, ks1 = key1, ks2 = key1 ^ 0x1BD11BDAu;
    x0 += ks0; x1 += ks1;
#define TFR(r) { x0 += x1; x1 = (x1 << (r)) | (x1 >> (32 - (r))); x1 ^= x0; }
    TFR(13) TFR(15) TFR(26) TFR(6)
    x0 += ks1; x1 += ks2 + 1u;
    TFR(17) TFR(29) TFR(16) TFR(24)
    x0 += ks2; x1 += ks0 + 2u;
    TFR(13) TFR(15) TFR(26) TFR(6)
    x0 += ks0; x1 += ks1 + 3u;
    TFR(17) TFR(29) TFR(16) TFR(24)
    x0 += ks1; x1 += ks2 + 4u;
    TFR(13) TFR(15) TFR(26) TFR(6)
    x0 += ks2; x1 += ks0 + 5u;
#undef TFR
    unsigned int bits = x0 ^ x1;
    float f = __uint_as_float((bits >> 9) | 0x3F800000u) - 1.0f;
    const float lo = -0.99999994f;
    float u = f * 2.0f + lo;
    u = fmaxf(u, lo);
    return 1.4142135623730951f * erfinvf(u);
}

// ---------------- fused encode: hid + qkv + single-pass attention per (b, head) ----------------
// grid 64 = b*4+n, 384 threads, 68KB dynamic smem.
__global__ void __launch_bounds__(384)
k_enc(const float* __restrict__ src,   // x (or xhat) + 63*S*F; stride ROW per b
      const float* __restrict__ w_enc, const float* __restrict__ b_enc,
      const float* __restrict__ wq, const float* __restrict__ bq,
      const float* __restrict__ wk, const float* __restrict__ bk,
      const float* __restrict__ wv, const float* __restrict__ bv) {
    extern __shared__ float sm[];
    float* hid = sm;                     // [128][33]
    float* qs  = sm + 128 * 33;
    float* ks  = sm + 2 * 128 * 33;
    float* vs  = sm + 3 * 128 * 33;
    int xid = blockIdx.x;                // b*4 + n
    int b = xid >> 2, n = xid & 3;
    int tid = threadIdx.x;
    const float* xb = src + (size_t)b * ROW;

    // Phase 1: hid[h][s] = b_enc[h] + sum_f x[s,f] * w_enc[f,h]  (2-way s ILP per thread)
    {
        int h = tid & 127;
        int grp = tid >> 7;              // 0..2
        int s0 = (grp == 0) ? 0 : (grp == 1 ? 11 : 22);
        int s1 = (grp == 0) ? 11 : (grp == 1 ? 22 : 32);
        float be = b_enc[h];
        int s = s0;
        for (; s + 2 <= s1; s += 2) {
            float a0 = be, a1 = be;
            const float* x0 = xb + s * Fx;
            const float* x1 = xb + (s + 1) * Fx;
            #pragma unroll 8
            for (int f = 0; f < Fx; ++f) {
                float w = w_enc[f * Hx + h];
                a0 = fmaf(x0[f], w, a0);
                a1 = fmaf(x1[f], w, a1);
            }
            hid[h * 33 + s] = a0;
            hid[h * 33 + s + 1] = a1;
        }
        if (s < s1) {
            float a0 = be;
            const float* x0 = xb + s * Fx;
            #pragma unroll 8
            for (int f = 0; f < Fx; ++f)
                a0 = fmaf(x0[f], w_enc[f * Hx + h], a0);
            hid[h * 33 + s] = a0;
        }
    }
    __syncthreads();

    // Phase 2: q/k/v[h][s] = bias + sum_sp hid[h][sp]*W[sp*128 + n*32+s]  (2-way s ILP)
    {
        int m = tid >> 7;                // 0=q 1=k 2=v
        int h = tid & 127;
        const float* W    = (m == 0) ? wq : (m == 1) ? wk : wv;
        const float* bias = (m == 0) ? bq : (m == 1) ? bk : bv;
        float* dst        = (m == 0) ? qs : (m == 1) ? ks : vs;
        const float scale = (m == 0) ? 0.08838834764831845f : 1.0f;
        for (int s = 0; s < Sx; s += 2) {
            float a0 = bias[n * Sx + s];
            float a1 = bias[n * Sx + s + 1];
            #pragma unroll
            for (int sp = 0; sp < Sx; ++sp) {
                float hval = hid[h * 33 + sp];
                a0 = fmaf(hval, W[sp * 128 + n * Sx + s], a0);
                a1 = fmaf(hval, W[sp * 128 + n * Sx + s + 1], a1);
            }
            dst[h * 33 + s] = a0 * scale;
            dst[h * 33 + s + 1] = a1 * scale;
        }
    }
    __syncthreads();

    // Phase 3: single-pass attention (scores are O(0.5): q carries 1/sqrt(128), so
    // softmax without max-subtraction is overflow-safe and ratio-identical).
    // threads 0..255: thread = h*2 + half.
    if (tid < 256) {
        int h = tid >> 1;
        int half = tid & 1;
        int off = half * 16;
        float qreg[16];
        #pragma unroll
        for (int s = 0; s < 16; ++s) qreg[s] = qs[h * 33 + off + s];

        float l = 0.f;
        float hacc[16];
        #pragma unroll
        for (int s = 0; s < 16; ++s) hacc[s] = 0.f;
        for (int g = 0; g < Hx; g += 2) {
            float sc0 = 0.f, sc1 = 0.f;
            #pragma unroll
            for (int s = 0; s < 16; ++s) {
                sc0 = fmaf(qreg[s], ks[g * 33 + off + s], sc0);
                sc1 = fmaf(qreg[s], ks[(g + 1) * 33 + off + s], sc1);
            }
            sc0 += __shfl_xor_sync(0xffffffffu, sc0, 1);
            sc1 += __shfl_xor_sync(0xffffffffu, sc1, 1);
            float p0 = __expf(sc0);
            float p1 = __expf(sc1);
            l += p0 + p1;
            #pragma unroll
            for (int s = 0; s < 16; ++s) {
                hacc[s] = fmaf(p0, vs[g * 33 + off + s], hacc[s]);
                hacc[s] = fmaf(p1, vs[(g + 1) * 33 + off + s], hacc[s]);
            }
        }
        float inv = 1.0f / l;
        #pragma unroll
        for (int s = 0; s < 16; ++s)
            g_att[(size_t)xid * HS + h * Sx + off + s] = hacc[s] * inv;
    }
}

// ---------------- fused head-mean+relu + gate partial GEMMs ----------------
// grid 192 = gate*64 + slice; 128 threads. Each slice covers 64 k-rows.
__global__ void k_gates2(const float* __restrict__ Wi, const float* __restrict__ Wg,
                         const float* __restrict__ Wo) {
    int gate = blockIdx.x >> 6;          // 0..2
    int ksl  = blockIdx.x & 63;          // 0..63
    int k0 = ksl * 64;
    int j = threadIdx.x;
    __shared__ float a_sm[Bx * 64];
    for (int idx = threadIdx.x; idx < Bx * 64; idx += 128) {
        int b = idx >> 6, rr = idx & 63;
        float v = g_att[(size_t)(b * 4 + 0) * HS + k0 + rr]
                + g_att[(size_t)(b * 4 + 1) * HS + k0 + rr]
                + g_att[(size_t)(b * 4 + 2) * HS + k0 + rr]
                + g_att[(size_t)(b * 4 + 3) * HS + k0 + rr];
        a_sm[idx] = fmaxf(0.25f * v, 0.f);
    }
    __syncthreads();
    const float* W = (gate == 0) ? Wi : (gate == 1) ? Wg : Wo;
    float acc[16];
    #pragma unroll
    for (int b = 0; b < 16; ++b) acc[b] = 0.f;
    #pragma unroll 8
    for (int rr = 0; rr < 64; ++rr) {
        float w = W[(size_t)(k0 + rr) * 128 + j];
        #pragma unroll
        for (int b = 0; b < 16; ++b)
            acc[b] = fmaf(a_sm[b * 64 + rr], w, acc[b]);
    }
    #pragma unroll
    for (int b = 0; b < 16; ++b)
        g_gpart[(size_t)blockIdx.x * (Bx * Hx) + b * 128 + j] = acc[b];
}

// ---------------- gate nonlins + h + fc + reparam z + KL partial (+ optional dec12) ----------------
__global__ void k_finz(const float* __restrict__ w_fc, const float* __restrict__ b_fc,
                       float* __restrict__ z_out, unsigned int key1,
                       const float* __restrict__ w1, const float* __restrict__ b1,
                       const float* __restrict__ w2, const float* __restrict__ b2,
                       double* __restrict__ klpart, int do_decode) {
    int b = blockIdx.x;
    int j = threadIdx.x;
    __shared__ float hv[128];
    __shared__ double dred[128];
    float si = 0.f, sg = 0.f, so = 0.f;
    #pragma unroll 8
    for (int p = 0; p < GSLICES; ++p) {
        si += g_gpart[(size_t)(0 * GSLICES + p) * 2048 + b * 128 + j];
        sg += g_gpart[(size_t)(1 * GSLICES + p) * 2048 + b * 128 + j];
        so += g_gpart[(size_t)(2 * GSLICES + p) * 2048 + b * 128 + j];
    }
    float iv = 1.f / (1.f + expf(-si));
    float gv = tanhf(sg);
    float ov = 1.f / (1.f + expf(-so));
    hv[j] = ov * tanhf(iv * gv);         // c = i*g since c0 = 0
    __syncthreads();
    float mu = b_fc[j], lv = b_fc[128 + j];
    #pragma unroll 8
    for (int k = 0; k < 128; ++k) {
        float hh = hv[k];
        mu = fmaf(hh, w_fc[k * 256 + j], mu);
        lv = fmaf(hh, w_fc[k * 256 + 128 + j], lv);
    }
    // KL partial: m^2 + (expm1(l) - l), cancellation-free, double
    {
        double md = (double)mu, ld = (double)lv;
        dred[j] = md * md + (expm1(ld) - ld);
    }
    float eps = tf_normal(key1, (unsigned)(b * 128 + j));
    float z = mu + eps * expf(0.5f * lv);
    z_out[b * 128 + j] = z;
    __syncthreads();
    for (int k = 64; k > 0; k >>= 1) {
        if (j < k) dred[j] += dred[j + k];
        __syncthreads();
    }
    if (j == 0) klpart[b] = dred[0];

    if (do_decode) {
        // dec layer 1+2 fused
        __shared__ float zsm[128], h1[128];
        zsm[j] = z;
        __syncthreads();
        float acc = b1[j];
        #pragma unroll 8
        for (int k = 0; k < 128; ++k) acc = fmaf(zsm[k], w1[k * 128 + j], acc);
        h1[j] = fmaxf(acc, 0.f);
        __syncthreads();
        acc = b2[j];
        #pragma unroll 8
        for (int k = 0; k < 128; ++k) acc = fmaf(h1[k], w2[k * 128 + j], acc);
        g_h2[b * 128 + j] = fmaxf(acc, 0.f);
    }
}

// ---------------- both KL finals: 2x16 doubles -> 2 scalars ----------------
__global__ void k_klboth(float* __restrict__ kl1, float* __restrict__ kl2) {
    int t = threadIdx.x;
    if (t == 0) {
        double s = 0.0;
        #pragma unroll
        for (int b = 0; b < Bx; ++b) s += g_klpart1[b];
        kl1[0] = (float)(0.5 * s / 2048.0);
    } else if (t == 1) {
        double s = 0.0;
        #pragma unroll
        for (int b = 0; b < Bx; ++b) s += g_klpart2[b];
        kl2[0] = (float)(0.5 * s / 2048.0);
    }
}

// ---------------- decoder big GEMM slice: [16,128]@[128, 4*ncols4] ----------------
// grid covers float4 columns [j4base, j4base + grid*128)
__global__ void __launch_bounds__(128)
k_dec3(const float* __restrict__ w3, const float* __restrict__ b3,
       float* __restrict__ xhat, int j4base) {
    __shared__ float hsm[2048];
    for (int i = threadIdx.x; i < 2048; i += 128) hsm[i] = g_h2[i];
    __syncthreads();
    int j4 = j4base + blockIdx.x * 128 + threadIdx.x;
    const float4* w4 = (const float4*)w3;
    float4 bias = ((const float4*)b3)[j4];
    float4 acc[16];
    #pragma unroll
    for (int b = 0; b < 16; ++b) acc[b] = bias;
    #pragma unroll 8
    for (int k = 0; k < 128; ++k) {
        float4 w = w4[(size_t)k * J4_ALL + j4];
        #pragma unroll
        for (int b = 0; b < 16; ++b) {
            float hb = hsm[b * 128 + k];
            acc[b].x = fmaf(hb, w.x, acc[b].x);
            acc[b].y = fmaf(hb, w.y, acc[b].y);
            acc[b].z = fmaf(hb, w.z, acc[b].z);
            acc[b].w = fmaf(hb, w.w, acc[b].w);
        }
    }
    float4* out4 = (float4*)xhat;
    #pragma unroll
    for (int b = 0; b < 16; ++b) out4[(size_t)b * J4_ALL + j4] = acc[b];
}

// ---------------- launch ----------------
extern "C" void kernel_launch(void* const* d_in, const int* in_sizes, int n_in,
                              void* d_out, int out_size) {
    const float* x     = (const float*)d_in[0];
    const float* w_enc = (const float*)d_in[1];
    const float* b_enc = (const float*)d_in[2];
    const float* wq = (const float*)d_in[3];
    const float* bq = (const float*)d_in[4];
    const float* wk = (const float*)d_in[5];
    const float* bk = (const float*)d_in[6];
    const float* wv = (const float*)d_in[7];
    const float* bv = (const float*)d_in[8];
    const float* W_ii = (const float*)d_in[9];
    // d_in[10..12]: W_hi, W_if, W_hf unused (c0 = 0 kills f gate and all W_h*)
    const float* W_ig = (const float*)d_in[13];
    const float* W_io = (const float*)d_in[15];
    const float* w_fc = (const float*)d_in[17];
    const float* b_fc = (const float*)d_in[18];
    const float* w_d1 = (const float*)d_in[19];
    const float* b_d1 = (const float*)d_in[20];
    const float* w_d2 = (const float*)d_in[21];
    const float* b_d2 = (const float*)d_in[22];
    const float* w_d3 = (const float*)d_in[23];
    const float* b_d3 = (const float*)d_in[24];

    float* out  = (float*)d_out;
    float* xhat = out;
    float* z1   = out + OFF_Z1;
    float* z2   = out + OFF_Z2;
    float* kl1  = out + OFF_KL1;
    float* kl2  = out + OFF_KL2;

    // One-time host resources (created on the uncaptured correctness call;
    // per-call work is identical thereafter).
    static cudaStream_t s_aux = nullptr;
    static cudaEvent_t ev_fork = nullptr, ev_join = nullptr;
    static bool smem_set = false;
    if (s_aux == nullptr) {
        cudaStreamCreateWithFlags(&s_aux, cudaStreamNonBlocking);
        cudaEventCreateWithFlags(&ev_fork, cudaEventDisableTiming);
        cudaEventCreateWithFlags(&ev_join, cudaEventDisableTiming);
    }
    if (!smem_set) {
        cudaFuncSetAttribute(k_enc, cudaFuncAttributeMaxDynamicSharedMemorySize, ENC_SMEM);
        smem_set = true;
    }

    double* klp1;  cudaGetSymbolAddress((void**)&klp1, g_klpart1);
    double* klp2;  cudaGetSymbolAddress((void**)&klp2, g_klpart2);

    // ---- encode 1 (only t = T-1 matters) ----
    k_enc<<<64, 384, ENC_SMEM>>>(x + T63OFF, w_enc, b_enc, wq, bq, wk, bk, wv, bv);
    k_gates2<<<192, 128>>>(W_ii, W_ig, W_io);
    k_finz<<<16, 128>>>(w_fc, b_fc, z1, 1u, w_d1, b_d1, w_d2, b_d2, klp1, 1);

    // ---- decode t=63 slice first: unblocks encode-2 ----
    k_dec3<<<8, 128>>>(w_d3, b_d3, xhat, J4_T63);

    // fork: rest of the decoder (98.4% of the 134MB stream) runs concurrently
    cudaEventRecord(ev_fork, 0);
    cudaStreamWaitEvent(s_aux, ev_fork, 0);
    k_dec3<<<504, 128, 0, s_aux>>>(w_d3, b_d3, xhat, 0);
    cudaEventRecord(ev_join, s_aux);

    // ---- encode 2 on x_hat[t=63] (hidden under dec3_rest) ----
    k_enc<<<64, 384, ENC_SMEM>>>(xhat + T63OFF, w_enc, b_enc, wq, bq, wk, bk, wv, bv);
    k_gates2<<<192, 128>>>(W_ii, W_ig, W_io);
    k_finz<<<16, 128>>>(w_fc, b_fc, z2, 2u, w_d1, b_d1, w_d2, b_d2, klp2, 0);
    k_klboth<<<1, 32>>>(kl1, kl2);

    // join
    cudaStreamWaitEvent(0, ev_join, 0);
}

// round 11
// speedup vs baseline: 3.4187x; 1.3307x over previous
#include <cuda_runtime.h>
#include <math.h>

// Dims
#define Bx 16
#define Tx 64
#define Sx 32
#define Fx 128
#define Hx 128
#define NHx 4
#define HS 4096      // H*S
#define ROW 262144   // T*S*F
#define T63OFF 258048 // 63*S*F

// Output layout (flattened tuple concat): x_hat1 | z1 | z2 | KL1 | KL2
#define OFF_Z1 4194304
#define OFF_Z2 4196352
#define OFF_KL1 4198400
#define OFF_KL2 4198401

#define GSLICES 64                          // k-slices per gate in k_gates2 (64 rows each)
// smem: hid,q,k,v each [128][33] floats
#define ENC_SMEM (4 * 128 * 33 * 4)

// float4 column split for k_dec3: t63 slice = [64512, 65536), rest = [0, 64512)
#define J4_T63 64512
#define J4_ALL 65536
#define T63_J4N 1024        // float4 columns in the t63 slice
#define T63_KC 16           // k-chunks (8 k each) in stage A

// ---------------- scratch (device globals; no allocation allowed) ----------------
__device__ float g_att[Bx * NHx * Hx * Sx];
__device__ float g_gpart[3 * GSLICES * Bx * Hx];
__device__ float g_h2[Bx * Hx];
__device__ double g_klpart1[Bx];
__device__ double g_klpart2[Bx];
__device__ float4 g_p63[T63_KC * Bx * T63_J4N];   // 4MB partials for t63 slice

// ---------------- JAX threefry2x32 (partitionable) -> normal ----------------
__device__ __forceinline__ float tf_normal(unsigned int key1, unsigned int i) {
    unsigned int x0 = 0u, x1 = i;
    unsigned int ks0 = 0u, ks1 = key1, ks2 = key1 ^ 0x1BD11BDAu;
    x0 += ks0; x1 += ks1;
#define TFR(r) { x0 += x1; x1 = (x1 << (r)) | (x1 >> (32 - (r))); x1 ^= x0; }
    TFR(13) TFR(15) TFR(26) TFR(6)
    x0 += ks1; x1 += ks2 + 1u;
    TFR(17) TFR(29) TFR(16) TFR(24)
    x0 += ks2; x1 += ks0 + 2u;
    TFR(13) TFR(15) TFR(26) TFR(6)
    x0 += ks0; x1 += ks1 + 3u;
    TFR(17) TFR(29) TFR(16) TFR(24)
    x0 += ks1; x1 += ks2 + 4u;
    TFR(13) TFR(15) TFR(26) TFR(6)
    x0 += ks2; x1 += ks0 + 5u;
#undef TFR
    unsigned int bits = x0 ^ x1;
    float f = __uint_as_float((bits >> 9) | 0x3F800000u) - 1.0f;
    const float lo = -0.99999994f;
    float u = f * 2.0f + lo;
    u = fmaxf(u, lo);
    return 1.4142135623730951f * erfinvf(u);
}

// ---------------- fused encode: hid + qkv + single-pass attention per (b, head) ----------------
__global__ void __launch_bounds__(384)
k_enc(const float* __restrict__ src,   // x (or xhat) + 63*S*F; stride ROW per b
      const float* __restrict__ w_enc, const float* __restrict__ b_enc,
      const float* __restrict__ wq, const float* __restrict__ bq,
      const float* __restrict__ wk, const float* __restrict__ bk,
      const float* __restrict__ wv, const float* __restrict__ bv) {
    extern __shared__ float sm[];
    float* hid = sm;                     // [128][33]
    float* qs  = sm + 128 * 33;
    float* ks  = sm + 2 * 128 * 33;
    float* vs  = sm + 3 * 128 * 33;
    int xid = blockIdx.x;                // b*4 + n
    int b = xid >> 2, n = xid & 3;
    int tid = threadIdx.x;
    const float* xb = src + (size_t)b * ROW;

    // Phase 1: hid[h][s] = b_enc[h] + sum_f x[s,f] * w_enc[f,h]  (2-way s ILP per thread)
    {
        int h = tid & 127;
        int grp = tid >> 7;              // 0..2
        int s0 = (grp == 0) ? 0 : (grp == 1 ? 11 : 22);
        int s1 = (grp == 0) ? 11 : (grp == 1 ? 22 : 32);
        float be = b_enc[h];
        int s = s0;
        for (; s + 2 <= s1; s += 2) {
            float a0 = be, a1 = be;
            const float* x0 = xb + s * Fx;
            const float* x1 = xb + (s + 1) * Fx;
            #pragma unroll 8
            for (int f = 0; f < Fx; ++f) {
                float w = w_enc[f * Hx + h];
                a0 = fmaf(x0[f], w, a0);
                a1 = fmaf(x1[f], w, a1);
            }
            hid[h * 33 + s] = a0;
            hid[h * 33 + s + 1] = a1;
        }
        if (s < s1) {
            float a0 = be;
            const float* x0 = xb + s * Fx;
            #pragma unroll 8
            for (int f = 0; f < Fx; ++f)
                a0 = fmaf(x0[f], w_enc[f * Hx + h], a0);
            hid[h * 33 + s] = a0;
        }
    }
    __syncthreads();

    // Phase 2: q/k/v[h][s] = bias + sum_sp hid[h][sp]*W[sp*128 + n*32+s]  (2-way s ILP)
    {
        int m = tid >> 7;                // 0=q 1=k 2=v
        int h = tid & 127;
        const float* W    = (m == 0) ? wq : (m == 1) ? wk : wv;
        const float* bias = (m == 0) ? bq : (m == 1) ? bk : bv;
        float* dst        = (m == 0) ? qs : (m == 1) ? ks : vs;
        const float scale = (m == 0) ? 0.08838834764831845f : 1.0f;
        for (int s = 0; s < Sx; s += 2) {
            float a0 = bias[n * Sx + s];
            float a1 = bias[n * Sx + s + 1];
            #pragma unroll
            for (int sp = 0; sp < Sx; ++sp) {
                float hval = hid[h * 33 + sp];
                a0 = fmaf(hval, W[sp * 128 + n * Sx + s], a0);
                a1 = fmaf(hval, W[sp * 128 + n * Sx + s + 1], a1);
            }
            dst[h * 33 + s] = a0 * scale;
            dst[h * 33 + s + 1] = a1 * scale;
        }
    }
    __syncthreads();

    // Phase 3: single-pass attention (scores O(0.5); safe without max-subtraction).
    if (tid < 256) {
        int h = tid >> 1;
        int half = tid & 1;
        int off = half * 16;
        float qreg[16];
        #pragma unroll
        for (int s = 0; s < 16; ++s) qreg[s] = qs[h * 33 + off + s];

        float l = 0.f;
        float hacc[16];
        #pragma unroll
        for (int s = 0; s < 16; ++s) hacc[s] = 0.f;
        for (int g = 0; g < Hx; g += 2) {
            float sc0 = 0.f, sc1 = 0.f;
            #pragma unroll
            for (int s = 0; s < 16; ++s) {
                sc0 = fmaf(qreg[s], ks[g * 33 + off + s], sc0);
                sc1 = fmaf(qreg[s], ks[(g + 1) * 33 + off + s], sc1);
            }
            sc0 += __shfl_xor_sync(0xffffffffu, sc0, 1);
            sc1 += __shfl_xor_sync(0xffffffffu, sc1, 1);
            float p0 = __expf(sc0);
            float p1 = __expf(sc1);
            l += p0 + p1;
            #pragma unroll
            for (int s = 0; s < 16; ++s) {
                hacc[s] = fmaf(p0, vs[g * 33 + off + s], hacc[s]);
                hacc[s] = fmaf(p1, vs[(g + 1) * 33 + off + s], hacc[s]);
            }
        }
        float inv = 1.0f / l;
        #pragma unroll
        for (int s = 0; s < 16; ++s)
            g_att[(size_t)xid * HS + h * Sx + off + s] = hacc[s] * inv;
    }
}

// ---------------- fused head-mean+relu + gate partial GEMMs ----------------
__global__ void k_gates2(const float* __restrict__ Wi, const float* __restrict__ Wg,
                         const float* __restrict__ Wo) {
    int gate = blockIdx.x >> 6;          // 0..2
    int ksl  = blockIdx.x & 63;          // 0..63
    int k0 = ksl * 64;
    int j = threadIdx.x;
    __shared__ float a_sm[Bx * 64];
    for (int idx = threadIdx.x; idx < Bx * 64; idx += 128) {
        int b = idx >> 6, rr = idx & 63;
        float v = g_att[(size_t)(b * 4 + 0) * HS + k0 + rr]
                + g_att[(size_t)(b * 4 + 1) * HS + k0 + rr]
                + g_att[(size_t)(b * 4 + 2) * HS + k0 + rr]
                + g_att[(size_t)(b * 4 + 3) * HS + k0 + rr];
        a_sm[idx] = fmaxf(0.25f * v, 0.f);
    }
    __syncthreads();
    const float* W = (gate == 0) ? Wi : (gate == 1) ? Wg : Wo;
    float acc[16];
    #pragma unroll
    for (int b = 0; b < 16; ++b) acc[b] = 0.f;
    #pragma unroll 8
    for (int rr = 0; rr < 64; ++rr) {
        float w = W[(size_t)(k0 + rr) * 128 + j];
        #pragma unroll
        for (int b = 0; b < 16; ++b)
            acc[b] = fmaf(a_sm[b * 64 + rr], w, acc[b]);
    }
    #pragma unroll
    for (int b = 0; b < 16; ++b)
        g_gpart[(size_t)blockIdx.x * (Bx * Hx) + b * 128 + j] = acc[b];
}

// ---------------- gate nonlins + h + fc + reparam z + KL partial (+ optional dec12) ----------------
__global__ void k_finz(const float* __restrict__ w_fc, const float* __restrict__ b_fc,
                       float* __restrict__ z_out, unsigned int key1,
                       const float* __restrict__ w1, const float* __restrict__ b1,
                       const float* __restrict__ w2, const float* __restrict__ b2,
                       double* __restrict__ klpart, int do_decode) {
    int b = blockIdx.x;
    int j = threadIdx.x;
    __shared__ float hv[128];
    __shared__ double dred[128];
    float si = 0.f, sg = 0.f, so = 0.f;
    #pragma unroll 8
    for (int p = 0; p < GSLICES; ++p) {
        si += g_gpart[(size_t)(0 * GSLICES + p) * 2048 + b * 128 + j];
        sg += g_gpart[(size_t)(1 * GSLICES + p) * 2048 + b * 128 + j];
        so += g_gpart[(size_t)(2 * GSLICES + p) * 2048 + b * 128 + j];
    }
    float iv = 1.f / (1.f + expf(-si));
    float gv = tanhf(sg);
    float ov = 1.f / (1.f + expf(-so));
    hv[j] = ov * tanhf(iv * gv);         // c = i*g since c0 = 0
    __syncthreads();
    float mu = b_fc[j], lv = b_fc[128 + j];
    #pragma unroll 8
    for (int k = 0; k < 128; ++k) {
        float hh = hv[k];
        mu = fmaf(hh, w_fc[k * 256 + j], mu);
        lv = fmaf(hh, w_fc[k * 256 + 128 + j], lv);
    }
    {
        double md = (double)mu, ld = (double)lv;
        dred[j] = md * md + (expm1(ld) - ld);
    }
    float eps = tf_normal(key1, (unsigned)(b * 128 + j));
    float z = mu + eps * expf(0.5f * lv);
    z_out[b * 128 + j] = z;
    __syncthreads();
    for (int k = 64; k > 0; k >>= 1) {
        if (j < k) dred[j] += dred[j + k];
        __syncthreads();
    }
    if (j == 0) klpart[b] = dred[0];

    if (do_decode) {
        __shared__ float zsm[128], h1[128];
        zsm[j] = z;
        __syncthreads();
        float acc = b1[j];
        #pragma unroll 8
        for (int k = 0; k < 128; ++k) acc = fmaf(zsm[k], w1[k * 128 + j], acc);
        h1[j] = fmaxf(acc, 0.f);
        __syncthreads();
        acc = b2[j];
        #pragma unroll 8
        for (int k = 0; k < 128; ++k) acc = fmaf(h1[k], w2[k * 128 + j], acc);
        g_h2[b * 128 + j] = fmaxf(acc, 0.f);
    }
}

// ---------------- both KL finals ----------------
__global__ void k_klboth(float* __restrict__ kl1, float* __restrict__ kl2) {
    int t = threadIdx.x;
    if (t == 0) {
        double s = 0.0;
        #pragma unroll
        for (int b = 0; b < Bx; ++b) s += g_klpart1[b];
        kl1[0] = (float)(0.5 * s / 2048.0);
    } else if (t == 1) {
        double s = 0.0;
        #pragma unroll
        for (int b = 0; b < Bx; ++b) s += g_klpart2[b];
        kl2[0] = (float)(0.5 * s / 2048.0);
    }
}

// ---------------- t63 slice stage A: partial GEMM over 8-k chunks ----------------
// grid 128 = colblk(8) * 16 + kc; 128 threads. Each thread: 8 loads, 16 float4 accs.
__global__ void __launch_bounds__(128)
k_d63a(const float* __restrict__ w3) {
    int colblk = blockIdx.x >> 4;        // 0..7
    int kc     = blockIdx.x & 15;        // 0..15
    int k0 = kc * 8;
    int tid = threadIdx.x;
    __shared__ float h2s[Bx][8];
    {
        int b = tid >> 3, kk = tid & 7;  // 128 threads exactly cover 16x8
        h2s[b][kk] = g_h2[b * 128 + k0 + kk];
    }
    __syncthreads();
    int cj = colblk * 128 + tid;         // 0..1023
    int j4 = J4_T63 + cj;
    const float4* w4 = (const float4*)w3;
    float4 acc[16];
    #pragma unroll
    for (int b = 0; b < 16; ++b) acc[b] = make_float4(0.f, 0.f, 0.f, 0.f);
    #pragma unroll
    for (int kk = 0; kk < 8; ++kk) {
        float4 w = w4[(size_t)(k0 + kk) * J4_ALL + j4];
        #pragma unroll
        for (int b = 0; b < 16; ++b) {
            float hb = h2s[b][kk];
            acc[b].x = fmaf(hb, w.x, acc[b].x);
            acc[b].y = fmaf(hb, w.y, acc[b].y);
            acc[b].z = fmaf(hb, w.z, acc[b].z);
            acc[b].w = fmaf(hb, w.w, acc[b].w);
        }
    }
    #pragma unroll
    for (int b = 0; b < 16; ++b)
        g_p63[((size_t)kc * Bx + b) * T63_J4N + cj] = acc[b];
}

// ---------------- t63 slice stage B: reduce 16 partials + bias -> xhat ----------------
// grid 128 x 128 = 16384 threads = one per (b, cj).
__global__ void __launch_bounds__(128)
k_d63b(const float* __restrict__ b3, float* __restrict__ xhat) {
    int idx = blockIdx.x * 128 + threadIdx.x;   // 0..16383
    int b  = idx >> 10;                         // 0..15
    int cj = idx & 1023;                        // 0..1023
    int j4 = J4_T63 + cj;
    float4 bias = ((const float4*)b3)[j4];
    float4 s = bias;
    #pragma unroll
    for (int kc = 0; kc < T63_KC; ++kc) {
        float4 p = g_p63[((size_t)kc * Bx + b) * T63_J4N + cj];
        s.x += p.x; s.y += p.y; s.z += p.z; s.w += p.w;
    }
    ((float4*)xhat)[(size_t)b * J4_ALL + j4] = s;
}

// ---------------- decoder big GEMM slice (rest columns) ----------------
__global__ void __launch_bounds__(128)
k_dec3(const float* __restrict__ w3, const float* __restrict__ b3,
       float* __restrict__ xhat, int j4base) {
    __shared__ float hsm[2048];
    for (int i = threadIdx.x; i < 2048; i += 128) hsm[i] = g_h2[i];
    __syncthreads();
    int j4 = j4base + blockIdx.x * 128 + threadIdx.x;
    const float4* w4 = (const float4*)w3;
    float4 bias = ((const float4*)b3)[j4];
    float4 acc[16];
    #pragma unroll
    for (int b = 0; b < 16; ++b) acc[b] = bias;
    #pragma unroll 8
    for (int k = 0; k < 128; ++k) {
        float4 w = w4[(size_t)k * J4_ALL + j4];
        #pragma unroll
        for (int b = 0; b < 16; ++b) {
            float hb = hsm[b * 128 + k];
            acc[b].x = fmaf(hb, w.x, acc[b].x);
            acc[b].y = fmaf(hb, w.y, acc[b].y);
            acc[b].z = fmaf(hb, w.z, acc[b].z);
            acc[b].w = fmaf(hb, w.w, acc[b].w);
        }
    }
    float4* out4 = (float4*)xhat;
    #pragma unroll
    for (int b = 0; b < 16; ++b) out4[(size_t)b * J4_ALL + j4] = acc[b];
}

// ---------------- launch ----------------
extern "C" void kernel_launch(void* const* d_in, const int* in_sizes, int n_in,
                              void* d_out, int out_size) {
    const float* x     = (const float*)d_in[0];
    const float* w_enc = (const float*)d_in[1];
    const float* b_enc = (const float*)d_in[2];
    const float* wq = (const float*)d_in[3];
    const float* bq = (const float*)d_in[4];
    const float* wk = (const float*)d_in[5];
    const float* bk = (const float*)d_in[6];
    const float* wv = (const float*)d_in[7];
    const float* bv = (const float*)d_in[8];
    const float* W_ii = (const float*)d_in[9];
    const float* W_ig = (const float*)d_in[13];
    const float* W_io = (const float*)d_in[15];
    const float* w_fc = (const float*)d_in[17];
    const float* b_fc = (const float*)d_in[18];
    const float* w_d1 = (const float*)d_in[19];
    const float* b_d1 = (const float*)d_in[20];
    const float* w_d2 = (const float*)d_in[21];
    const float* b_d2 = (const float*)d_in[22];
    const float* w_d3 = (const float*)d_in[23];
    const float* b_d3 = (const float*)d_in[24];

    float* out  = (float*)d_out;
    float* xhat = out;
    float* z1   = out + OFF_Z1;
    float* z2   = out + OFF_Z2;
    float* kl1  = out + OFF_KL1;
    float* kl2  = out + OFF_KL2;

    static cudaStream_t s_aux = nullptr;
    static cudaEvent_t ev_fork = nullptr, ev_join = nullptr;
    static bool smem_set = false;
    if (s_aux == nullptr) {
        cudaStreamCreateWithFlags(&s_aux, cudaStreamNonBlocking);
        cudaEventCreateWithFlags(&ev_fork, cudaEventDisableTiming);
        cudaEventCreateWithFlags(&ev_join, cudaEventDisableTiming);
    }
    if (!smem_set) {
        cudaFuncSetAttribute(k_enc, cudaFuncAttributeMaxDynamicSharedMemorySize, ENC_SMEM);
        smem_set = true;
    }

    double* klp1;  cudaGetSymbolAddress((void**)&klp1, g_klpart1);
    double* klp2;  cudaGetSymbolAddress((void**)&klp2, g_klpart2);

    // ---- encode 1 (only t = T-1 matters) ----
    k_enc<<<64, 384, ENC_SMEM>>>(x + T63OFF, w_enc, b_enc, wq, bq, wk, bk, wv, bv);
    k_gates2<<<192, 128>>>(W_ii, W_ig, W_io);
    k_finz<<<16, 128>>>(w_fc, b_fc, z1, 1u, w_d1, b_d1, w_d2, b_d2, klp1, 1);

    // fork right after finz: dec3_rest runs concurrently with the t63 slice + encode 2
    cudaEventRecord(ev_fork, 0);
    cudaStreamWaitEvent(s_aux, ev_fork, 0);
    k_dec3<<<504, 128, 0, s_aux>>>(w_d3, b_d3, xhat, 0);
    cudaEventRecord(ev_join, s_aux);

    // ---- t63 slice (parallel two-stage), unblocks encode 2 fast ----
    k_d63a<<<128, 128>>>(w_d3);
    k_d63b<<<128, 128>>>(b_d3, xhat);

    // ---- encode 2 on x_hat[t=63] (hidden under dec3_rest) ----
    k_enc<<<64, 384, ENC_SMEM>>>(xhat + T63OFF, w_enc, b_enc, wq, bq, wk, bk, wv, bv);
    k_gates2<<<192, 128>>>(W_ii, W_ig, W_io);
    k_finz<<<16, 128>>>(w_fc, b_fc, z2, 2u, w_d1, b_d1, w_d2, b_d2, klp2, 0);
    k_klboth<<<1, 32>>>(kl1, kl2);

    // join
    cudaStreamWaitEvent(0, ev_join, 0);
}

// round 13
// speedup vs baseline: 3.8640x; 1.1303x over previous
#include <cuda_runtime.h>
#include <math.h>

// Dims
#define Bx 16
#define Tx 64
#define Sx 32
#define Fx 128
#define Hx 128
#define NHx 4
#define HS 4096      // H*S
#define ROW 262144   // T*S*F
#define T63OFF 258048 // 63*S*F

// Output layout (flattened tuple concat): x_hat1 | z1 | z2 | KL1 | KL2
#define OFF_Z1 4194304
#define OFF_Z2 4196352
#define OFF_KL1 4198400
#define OFF_KL2 4198401

#define GSLICES 128                         // k-slices per gate in k_gates2 (32 rows each)
// smem: hid,q,k,v each [128][33] floats + wq/wk/wv [3][32][128]
#define ENC_SMEM ((4 * 128 * 33 + 3 * 4096) * 4)

// float4 column split for k_dec3: t63 slice = [64512, 65536), rest = [0, 64512)
#define J4_T63 64512
#define J4_ALL 65536
#define T63_J4N 1024        // float4 columns in the t63 slice
#define T63_KC 16           // k-chunks (8 k each) in stage A

// ---------------- scratch (device globals; no allocation allowed) ----------------
__device__ float g_att[Bx * NHx * Hx * Sx];
__device__ float g_gpart[3 * GSLICES * Bx * Hx];   // 3MB partials
__device__ float g_h2[Bx * Hx];
__device__ double g_klpart1[Bx];
__device__ double g_klpart2[Bx];
__device__ float4 g_p63[T63_KC * Bx * T63_J4N];    // 4MB partials for t63 slice

// ---------------- JAX threefry2x32 (partitionable) -> normal ----------------
__device__ __forceinline__ float tf_normal(unsigned int key1, unsigned int i) {
    unsigned int x0 = 0u, x1 = i;
    unsigned int ks0 = 0u, ks1 = key1, ks2 = key1 ^ 0x1BD11BDAu;
    x0 += ks0; x1 += ks1;
#define TFR(r) { x0 += x1; x1 = (x1 << (r)) | (x1 >> (32 - (r))); x1 ^= x0; }
    TFR(13) TFR(15) TFR(26) TFR(6)
    x0 += ks1; x1 += ks2 + 1u;
    TFR(17) TFR(29) TFR(16) TFR(24)
    x0 += ks2; x1 += ks0 + 2u;
    TFR(13) TFR(15) TFR(26) TFR(6)
    x0 += ks0; x1 += ks1 + 3u;
    TFR(17) TFR(29) TFR(16) TFR(24)
    x0 += ks1; x1 += ks2 + 4u;
    TFR(13) TFR(15) TFR(26) TFR(6)
    x0 += ks2; x1 += ks0 + 5u;
#undef TFR
    unsigned int bits = x0 ^ x1;
    float f = __uint_as_float((bits >> 9) | 0x3F800000u) - 1.0f;
    const float lo = -0.99999994f;
    float u = f * 2.0f + lo;
    u = fmaxf(u, lo);
    return 1.4142135623730951f * erfinvf(u);
}

// ---------------- fused encode: hid + qkv + single-pass attention per (b, head) ----------------
__global__ void __launch_bounds__(384)
k_enc(const float* __restrict__ src,   // x (or xhat) + 63*S*F; stride ROW per b
      const float* __restrict__ w_enc, const float* __restrict__ b_enc,
      const float* __restrict__ wq, const float* __restrict__ bq,
      const float* __restrict__ wk, const float* __restrict__ bk,
      const float* __restrict__ wv, const float* __restrict__ bv) {
    extern __shared__ float sm[];
    float* hid = sm;                     // [128][33]
    float* qs  = sm + 128 * 33;
    float* ks  = sm + 2 * 128 * 33;
    float* vs  = sm + 3 * 128 * 33;
    float* wsm = sm + 4 * 128 * 33;      // [3][32][128] = wq|wk|wv
    int xid = blockIdx.x;                // b*4 + n
    int b = xid >> 2, n = xid & 3;
    int tid = threadIdx.x;
    const float* xb = src + (size_t)b * ROW;

    // Stage qkv weight matrices into smem (overlaps with phase-1 gmem work)
    for (int i = tid; i < 3 * 4096; i += 384) {
        const float* W = (i < 4096) ? wq : (i < 8192 ? wk : wv);
        wsm[i] = W[i & 4095];
    }

    // Phase 1: hid[h][s] = b_enc[h] + sum_f x[s,f] * w_enc[f,h]  (2-way s ILP per thread)
    {
        int h = tid & 127;
        int grp = tid >> 7;              // 0..2
        int s0 = (grp == 0) ? 0 : (grp == 1 ? 11 : 22);
        int s1 = (grp == 0) ? 11 : (grp == 1 ? 22 : 32);
        float be = b_enc[h];
        int s = s0;
        for (; s + 2 <= s1; s += 2) {
            float a0 = be, a1 = be;
            const float* x0 = xb + s * Fx;
            const float* x1 = xb + (s + 1) * Fx;
            #pragma unroll 8
            for (int f = 0; f < Fx; ++f) {
                float w = w_enc[f * Hx + h];
                a0 = fmaf(x0[f], w, a0);
                a1 = fmaf(x1[f], w, a1);
            }
            hid[h * 33 + s] = a0;
            hid[h * 33 + s + 1] = a1;
        }
        if (s < s1) {
            float a0 = be;
            const float* x0 = xb + s * Fx;
            #pragma unroll 8
            for (int f = 0; f < Fx; ++f)
                a0 = fmaf(x0[f], w_enc[f * Hx + h], a0);
            hid[h * 33 + s] = a0;
        }
    }
    __syncthreads();

    // Phase 2: q/k/v[h][s] = bias + sum_sp hid[h][sp]*W[sp][n*32+s]
    // hid row in registers; W via float4 smem broadcasts.
    {
        int m = tid >> 7;                // 0=q 1=k 2=v
        int h = tid & 127;
        const float* Wm   = wsm + m * 4096;
        const float* bias = (m == 0) ? bq : (m == 1) ? bk : bv;
        float* dst        = (m == 0) ? qs : (m == 1) ? ks : vs;
        const float scale = (m == 0) ? 0.08838834764831845f : 1.0f;
        float hreg[32];
        #pragma unroll
        for (int sp = 0; sp < 32; ++sp) hreg[sp] = hid[h * 33 + sp];
        for (int s = 0; s < Sx; s += 4) {
            float4 acc = *(const float4*)&bias[n * Sx + s];
            #pragma unroll
            for (int sp = 0; sp < 32; ++sp) {
                float4 w = *(const float4*)&Wm[sp * 128 + n * Sx + s];
                float hv = hreg[sp];
                acc.x = fmaf(hv, w.x, acc.x);
                acc.y = fmaf(hv, w.y, acc.y);
                acc.z = fmaf(hv, w.z, acc.z);
                acc.w = fmaf(hv, w.w, acc.w);
            }
            dst[h * 33 + s]     = acc.x * scale;
            dst[h * 33 + s + 1] = acc.y * scale;
            dst[h * 33 + s + 2] = acc.z * scale;
            dst[h * 33 + s + 3] = acc.w * scale;
        }
    }
    __syncthreads();

    // Phase 3: single-pass attention (scores O(0.5); safe without max-subtraction).
    if (tid < 256) {
        int h = tid >> 1;
        int half = tid & 1;
        int off = half * 16;
        float qreg[16];
        #pragma unroll
        for (int s = 0; s < 16; ++s) qreg[s] = qs[h * 33 + off + s];

        float l = 0.f;
        float hacc[16];
        #pragma unroll
        for (int s = 0; s < 16; ++s) hacc[s] = 0.f;
        for (int g = 0; g < Hx; g += 2) {
            float sc0 = 0.f, sc1 = 0.f;
            #pragma unroll
            for (int s = 0; s < 16; ++s) {
                sc0 = fmaf(qreg[s], ks[g * 33 + off + s], sc0);
                sc1 = fmaf(qreg[s], ks[(g + 1) * 33 + off + s], sc1);
            }
            sc0 += __shfl_xor_sync(0xffffffffu, sc0, 1);
            sc1 += __shfl_xor_sync(0xffffffffu, sc1, 1);
            float p0 = __expf(sc0);
            float p1 = __expf(sc1);
            l += p0 + p1;
            #pragma unroll
            for (int s = 0; s < 16; ++s) {
                hacc[s] = fmaf(p0, vs[g * 33 + off + s], hacc[s]);
                hacc[s] = fmaf(p1, vs[(g + 1) * 33 + off + s], hacc[s]);
            }
        }
        float inv = 1.0f / l;
        #pragma unroll
        for (int s = 0; s < 16; ++s)
            g_att[(size_t)xid * HS + h * Sx + off + s] = hacc[s] * inv;
    }
}

// ---------------- fused head-mean+relu + gate partial GEMMs ----------------
// grid 384 = gate*128 + slice; 128 threads. Each slice covers 32 k-rows.
__global__ void k_gates2(const float* __restrict__ Wi, const float* __restrict__ Wg,
                         const float* __restrict__ Wo) {
    int gate = blockIdx.x >> 7;          // 0..2
    int ksl  = blockIdx.x & 127;         // 0..127
    int k0 = ksl * 32;
    int j = threadIdx.x;
    __shared__ float a_sm[Bx * 32];
    for (int idx = threadIdx.x; idx < Bx * 32; idx += 128) {
        int b = idx >> 5, rr = idx & 31;
        float v = g_att[(size_t)(b * 4 + 0) * HS + k0 + rr]
                + g_att[(size_t)(b * 4 + 1) * HS + k0 + rr]
                + g_att[(size_t)(b * 4 + 2) * HS + k0 + rr]
                + g_att[(size_t)(b * 4 + 3) * HS + k0 + rr];
        a_sm[idx] = fmaxf(0.25f * v, 0.f);
    }
    __syncthreads();
    const float* W = (gate == 0) ? Wi : (gate == 1) ? Wg : Wo;
    float acc[16];
    #pragma unroll
    for (int b = 0; b < 16; ++b) acc[b] = 0.f;
    #pragma unroll 8
    for (int rr = 0; rr < 32; ++rr) {
        float w = W[(size_t)(k0 + rr) * 128 + j];
        #pragma unroll
        for (int b = 0; b < 16; ++b)
            acc[b] = fmaf(a_sm[b * 32 + rr], w, acc[b]);
    }
    #pragma unroll
    for (int b = 0; b < 16; ++b)
        g_gpart[(size_t)blockIdx.x * (Bx * Hx) + b * 128 + j] = acc[b];
}

// ---------------- gate nonlins + h + fc + reparam z + KL partial (+ optional dec12) ----------------
__global__ void k_finz(const float* __restrict__ w_fc, const float* __restrict__ b_fc,
                       float* __restrict__ z_out, unsigned int key1,
                       const float* __restrict__ w1, const float* __restrict__ b1,
                       const float* __restrict__ w2, const float* __restrict__ b2,
                       double* __restrict__ klpart, int do_decode) {
    int b = blockIdx.x;
    int j = threadIdx.x;
    __shared__ float hv[128];
    __shared__ double dred[128];
    float si = 0.f, sg = 0.f, so = 0.f;
    #pragma unroll 16
    for (int p = 0; p < GSLICES; ++p) {
        si += g_gpart[(size_t)(0 * GSLICES + p) * 2048 + b * 128 + j];
        sg += g_gpart[(size_t)(1 * GSLICES + p) * 2048 + b * 128 + j];
        so += g_gpart[(size_t)(2 * GSLICES + p) * 2048 + b * 128 + j];
    }
    float iv = 1.f / (1.f + expf(-si));
    float gv = tanhf(sg);
    float ov = 1.f / (1.f + expf(-so));
    hv[j] = ov * tanhf(iv * gv);         // c = i*g since c0 = 0
    __syncthreads();
    float mu = b_fc[j], lv = b_fc[128 + j];
    #pragma unroll 8
    for (int k = 0; k < 128; ++k) {
        float hh = hv[k];
        mu = fmaf(hh, w_fc[k * 256 + j], mu);
        lv = fmaf(hh, w_fc[k * 256 + 128 + j], lv);
    }
    {
        double md = (double)mu, ld = (double)lv;
        dred[j] = md * md + (expm1(ld) - ld);
    }
    float eps = tf_normal(key1, (unsigned)(b * 128 + j));
    float z = mu + eps * expf(0.5f * lv);
    z_out[b * 128 + j] = z;
    __syncthreads();
    for (int k = 64; k > 0; k >>= 1) {
        if (j < k) dred[j] += dred[j + k];
        __syncthreads();
    }
    if (j == 0) klpart[b] = dred[0];

    if (do_decode) {
        __shared__ float zsm[128], h1[128];
        zsm[j] = z;
        __syncthreads();
        float acc = b1[j];
        #pragma unroll 8
        for (int k = 0; k < 128; ++k) acc = fmaf(zsm[k], w1[k * 128 + j], acc);
        h1[j] = fmaxf(acc, 0.f);
        __syncthreads();
        acc = b2[j];
        #pragma unroll 8
        for (int k = 0; k < 128; ++k) acc = fmaf(h1[k], w2[k * 128 + j], acc);
        g_h2[b * 128 + j] = fmaxf(acc, 0.f);
    }
}

// ---------------- both KL finals ----------------
__global__ void k_klboth(float* __restrict__ kl1, float* __restrict__ kl2) {
    int t = threadIdx.x;
    if (t == 0) {
        double s = 0.0;
        #pragma unroll
        for (int b = 0; b < Bx; ++b) s += g_klpart1[b];
        kl1[0] = (float)(0.5 * s / 2048.0);
    } else if (t == 1) {
        double s = 0.0;
        #pragma unroll
        for (int b = 0; b < Bx; ++b) s += g_klpart2[b];
        kl2[0] = (float)(0.5 * s / 2048.0);
    }
}

// ---------------- t63 slice stage A: partial GEMM over 8-k chunks ----------------
__global__ void __launch_bounds__(128)
k_d63a(const float* __restrict__ w3) {
    int colblk = blockIdx.x >> 4;        // 0..7
    int kc     = blockIdx.x & 15;        // 0..15
    int k0 = kc * 8;
    int tid = threadIdx.x;
    __shared__ float h2s[Bx][8];
    {
        int b = tid >> 3, kk = tid & 7;
        h2s[b][kk] = g_h2[b * 128 + k0 + kk];
    }
    __syncthreads();
    int cj = colblk * 128 + tid;         // 0..1023
    int j4 = J4_T63 + cj;
    const float4* w4 = (const float4*)w3;
    float4 acc[16];
    #pragma unroll
    for (int b = 0; b < 16; ++b) acc[b] = make_float4(0.f, 0.f, 0.f, 0.f);
    #pragma unroll
    for (int kk = 0; kk < 8; ++kk) {
        float4 w = w4[(size_t)(k0 + kk) * J4_ALL + j4];
        #pragma unroll
        for (int b = 0; b < 16; ++b) {
            float hb = h2s[b][kk];
            acc[b].x = fmaf(hb, w.x, acc[b].x);
            acc[b].y = fmaf(hb, w.y, acc[b].y);
            acc[b].z = fmaf(hb, w.z, acc[b].z);
            acc[b].w = fmaf(hb, w.w, acc[b].w);
        }
    }
    #pragma unroll
    for (int b = 0; b < 16; ++b)
        g_p63[((size_t)kc * Bx + b) * T63_J4N + cj] = acc[b];
}

// ---------------- t63 slice stage B: reduce 16 partials + bias -> xhat ----------------
__global__ void __launch_bounds__(128)
k_d63b(const float* __restrict__ b3, float* __restrict__ xhat) {
    int idx = blockIdx.x * 128 + threadIdx.x;   // 0..16383
    int b  = idx >> 10;
    int cj = idx & 1023;
    int j4 = J4_T63 + cj;
    float4 bias = ((const float4*)b3)[j4];
    float4 s = bias;
    #pragma unroll
    for (int kc = 0; kc < T63_KC; ++kc) {
        float4 p = g_p63[((size_t)kc * Bx + b) * T63_J4N + cj];
        s.x += p.x; s.y += p.y; s.z += p.z; s.w += p.w;
    }
    ((float4*)xhat)[(size_t)b * J4_ALL + j4] = s;
}

// ---------------- decoder big GEMM (rest columns), b split into halves ----------------
// grid 1008 = colblk(504)*2 + bh; 128 threads; 8 float4 accumulators per thread.
__global__ void __launch_bounds__(128)
k_dec3(const float* __restrict__ w3, const float* __restrict__ b3,
       float* __restrict__ xhat) {
    int bh     = blockIdx.x & 1;         // 0/1: b in [bh*8, bh*8+8)
    int colblk = blockIdx.x >> 1;        // 0..503
    __shared__ float hsm[8 * 128];
    for (int i = threadIdx.x; i < 8 * 128; i += 128)
        hsm[i] = g_h2[bh * 8 * 128 + i];
    __syncthreads();
    int j4 = colblk * 128 + threadIdx.x;
    const float4* w4 = (const float4*)w3;
    float4 bias = ((const float4*)b3)[j4];
    float4 acc[8];
    #pragma unroll
    for (int b = 0; b < 8; ++b) acc[b] = bias;
    #pragma unroll 8
    for (int k = 0; k < 128; ++k) {
        float4 w = w4[(size_t)k * J4_ALL + j4];
        #pragma unroll
        for (int b = 0; b < 8; ++b) {
            float hb = hsm[b * 128 + k];
            acc[b].x = fmaf(hb, w.x, acc[b].x);
            acc[b].y = fmaf(hb, w.y, acc[b].y);
            acc[b].z = fmaf(hb, w.z, acc[b].z);
            acc[b].w = fmaf(hb, w.w, acc[b].w);
        }
    }
    float4* out4 = (float4*)xhat;
    #pragma unroll
    for (int b = 0; b < 8; ++b)
        out4[(size_t)(bh * 8 + b) * J4_ALL + j4] = acc[b];
}

// ---------------- launch ----------------
extern "C" void kernel_launch(void* const* d_in, const int* in_sizes, int n_in,
                              void* d_out, int out_size) {
    const float* x     = (const float*)d_in[0];
    const float* w_enc = (const float*)d_in[1];
    const float* b_enc = (const float*)d_in[2];
    const float* wq = (const float*)d_in[3];
    const float* bq = (const float*)d_in[4];
    const float* wk = (const float*)d_in[5];
    const float* bk = (const float*)d_in[6];
    const float* wv = (const float*)d_in[7];
    const float* bv = (const float*)d_in[8];
    const float* W_ii = (const float*)d_in[9];
    const float* W_ig = (const float*)d_in[13];
    const float* W_io = (const float*)d_in[15];
    const float* w_fc = (const float*)d_in[17];
    const float* b_fc = (const float*)d_in[18];
    const float* w_d1 = (const float*)d_in[19];
    const float* b_d1 = (const float*)d_in[20];
    const float* w_d2 = (const float*)d_in[21];
    const float* b_d2 = (const float*)d_in[22];
    const float* w_d3 = (const float*)d_in[23];
    const float* b_d3 = (const float*)d_in[24];

    float* out  = (float*)d_out;
    float* xhat = out;
    float* z1   = out + OFF_Z1;
    float* z2   = out + OFF_Z2;
    float* kl1  = out + OFF_KL1;
    float* kl2  = out + OFF_KL2;

    static cudaStream_t s_aux = nullptr;
    static cudaEvent_t ev_fork = nullptr, ev_join = nullptr;
    static bool smem_set = false;
    if (s_aux == nullptr) {
        cudaStreamCreateWithFlags(&s_aux, cudaStreamNonBlocking);
        cudaEventCreateWithFlags(&ev_fork, cudaEventDisableTiming);
        cudaEventCreateWithFlags(&ev_join, cudaEventDisableTiming);
    }
    if (!smem_set) {
        cudaFuncSetAttribute(k_enc, cudaFuncAttributeMaxDynamicSharedMemorySize, ENC_SMEM);
        smem_set = true;
    }

    double* klp1;  cudaGetSymbolAddress((void**)&klp1, g_klpart1);
    double* klp2;  cudaGetSymbolAddress((void**)&klp2, g_klpart2);

    // ---- encode 1 (only t = T-1 matters) ----
    k_enc<<<64, 384, ENC_SMEM>>>(x + T63OFF, w_enc, b_enc, wq, bq, wk, bk, wv, bv);
    k_gates2<<<384, 128>>>(W_ii, W_ig, W_io);
    k_finz<<<16, 128>>>(w_fc, b_fc, z1, 1u, w_d1, b_d1, w_d2, b_d2, klp1, 1);

    // fork right after finz: dec3_rest runs concurrently with the t63 slice + encode 2
    cudaEventRecord(ev_fork, 0);
    cudaStreamWaitEvent(s_aux, ev_fork, 0);
    k_dec3<<<1008, 128, 0, s_aux>>>(w_d3, b_d3, xhat);
    cudaEventRecord(ev_join, s_aux);

    // ---- t63 slice (parallel two-stage), unblocks encode 2 fast ----
    k_d63a<<<128, 128>>>(w_d3);
    k_d63b<<<128, 128>>>(b_d3, xhat);

    // ---- encode 2 on x_hat[t=63] (hidden under dec3_rest) ----
    k_enc<<<64, 384, ENC_SMEM>>>(xhat + T63OFF, w_enc, b_enc, wq, bq, wk, bk, wv, bv);
    k_gates2<<<384, 128>>>(W_ii, W_ig, W_io);
    k_finz<<<16, 128>>>(w_fc, b_fc, z2, 2u, w_d1, b_d1, w_d2, b_d2, klp2, 0);
    k_klboth<<<1, 32>>>(kl1, kl2);

    // join
    cudaStreamWaitEvent(0, ev_join, 0);
}